// round 2
// baseline (speedup 1.0000x reference)
#include <cuda_runtime.h>
#include <cstddef>

#define Bdim 4
#define Tdim 2048
#define Cdim 1024
#define Hdim 16
#define Ddim 64
#define C3   3072
#define Mrows (Bdim * Tdim)   // 8192

// Scratch: qkv [8192, 3072] and attention output [8192, 1024] (fp32)
__device__ float g_qkv[(size_t)Mrows * C3];
__device__ float g_att[(size_t)Mrows * Cdim];

// ---------------------------------------------------------------------------
// Packed fp32x2 helpers (sm_100+ packed-double-width fp32 pipe)
// ---------------------------------------------------------------------------
typedef unsigned long long u64;

__device__ __forceinline__ u64 ffma2(u64 a, u64 b, u64 c) {
    u64 d;
    asm("fma.rn.f32x2 %0, %1, %2, %3;" : "=l"(d) : "l"(a), "l"(b), "l"(c));
    return d;
}
__device__ __forceinline__ u64 fmul2(u64 a, u64 b) {
    u64 d;
    asm("mul.rn.f32x2 %0, %1, %2;" : "=l"(d) : "l"(a), "l"(b));
    return d;
}
__device__ __forceinline__ u64 pk2(float x, float y) {
    u64 r;
    asm("mov.b64 %0, {%1, %2};" : "=l"(r) : "f"(x), "f"(y));
    return r;
}
__device__ __forceinline__ void upk2(u64 p, float& x, float& y) {
    asm("mov.b64 {%0, %1}, %2;" : "=f"(x), "=f"(y) : "l"(p));
}

// ---------------------------------------------------------------------------
// GEMM: C[M,N] = A[M,K] @ B[K,N] + bias[N]
// 128x128x16 tile, 256 threads, 8x8 per-thread microtile via fp32x2 FFMA.
// A tile stored transposed AND lane-duplicated (float2 = (a,a)) so a single
// LDS.64 yields a packed broadcast operand for fma.rn.f32x2.
// ---------------------------------------------------------------------------
__global__ __launch_bounds__(256) void gemm_bias_kernel(
    const float* __restrict__ A, const float* __restrict__ B,
    const float* __restrict__ bias, float* __restrict__ C,
    int M, int N, int K)
{
    __shared__ float2 As2[16][128];   // (a,a) duplicated, transposed: [k][row]
    __shared__ float2 Bs2[16][64];    // natural pairs: [k][col/2]

    const int tid = threadIdx.x;
    const int bm = blockIdx.y * 128;
    const int bn = blockIdx.x * 128;
    const int tx = tid & 15;        // 16 col groups (8 cols = 4 pairs each)
    const int ty = tid >> 4;        // 16 row groups (8 rows each)

    u64 acc2[8][4];                 // [row][colpair], zero bits == (0.f,0.f)
#pragma unroll
    for (int i = 0; i < 8; i++)
#pragma unroll
        for (int j = 0; j < 4; j++) acc2[i][j] = 0ull;

    const float* Aptr = A + (size_t)bm * K;
    const float* Bptr = B + bn;

    for (int k0 = 0; k0 < K; k0 += 16) {
        // Load A tile 128x16 (512 float4, 2 per thread), store transposed+dup
#pragma unroll
        for (int i = 0; i < 2; i++) {
            int lin = tid + i * 256;          // 0..511
            int row = lin >> 2;               // 0..127
            int c4  = lin & 3;                // 0..3
            float4 v = *reinterpret_cast<const float4*>(
                Aptr + (size_t)row * K + k0 + c4 * 4);
            As2[c4 * 4 + 0][row] = make_float2(v.x, v.x);
            As2[c4 * 4 + 1][row] = make_float2(v.y, v.y);
            As2[c4 * 4 + 2][row] = make_float2(v.z, v.z);
            As2[c4 * 4 + 3][row] = make_float2(v.w, v.w);
        }
        // Load B tile 16x128 (512 float4, 2 per thread)
#pragma unroll
        for (int i = 0; i < 2; i++) {
            int lin = tid + i * 256;
            int row = lin >> 5;               // 0..15
            int c4  = lin & 31;               // 0..31
            float4 v = *reinterpret_cast<const float4*>(
                Bptr + (size_t)(k0 + row) * N + c4 * 4);
            Bs2[row][c4 * 2 + 0] = make_float2(v.x, v.y);
            Bs2[row][c4 * 2 + 1] = make_float2(v.z, v.w);
        }
        __syncthreads();

#pragma unroll
        for (int kk = 0; kk < 16; kk++) {
            u64 a2[8], b2[4];
#pragma unroll
            for (int i = 0; i < 8; i++)
                a2[i] = *reinterpret_cast<const u64*>(&As2[kk][ty * 8 + i]);
#pragma unroll
            for (int j = 0; j < 4; j++)
                b2[j] = *reinterpret_cast<const u64*>(&Bs2[kk][tx * 4 + j]);
#pragma unroll
            for (int i = 0; i < 8; i++)
#pragma unroll
                for (int j = 0; j < 4; j++)
                    acc2[i][j] = ffma2(a2[i], b2[j], acc2[i][j]);
        }
        __syncthreads();
    }

#pragma unroll
    for (int i = 0; i < 8; i++) {
        int row = bm + ty * 8 + i;
        int col = bn + tx * 8;
        float c0,c1,c2,c3,c4,c5,c6,c7;
        upk2(acc2[i][0], c0, c1);
        upk2(acc2[i][1], c2, c3);
        upk2(acc2[i][2], c4, c5);
        upk2(acc2[i][3], c6, c7);
        float4 o0, o1;
        o0.x = c0 + bias[col + 0]; o0.y = c1 + bias[col + 1];
        o0.z = c2 + bias[col + 2]; o0.w = c3 + bias[col + 3];
        o1.x = c4 + bias[col + 4]; o1.y = c5 + bias[col + 5];
        o1.z = c6 + bias[col + 6]; o1.w = c7 + bias[col + 7];
        *reinterpret_cast<float4*>(C + (size_t)row * N + col)     = o0;
        *reinterpret_cast<float4*>(C + (size_t)row * N + col + 4) = o1;
    }
}

// ---------------------------------------------------------------------------
// Causal flash attention, fp32x2. One thread owns one query row.
// qkv layout: [b*T+t][3072] with q=[0,1024), k=[1024,2048), v=[2048,3072).
// Output written in [B,T,C] layout.
// Grid: (T/128, B*H), 128 threads.
// ---------------------------------------------------------------------------
__global__ __launch_bounds__(128) void attn_kernel(
    const float* __restrict__ qkv, float* __restrict__ out)
{
    __shared__ float Ks[64][64];
    __shared__ float Vs[64][64];

    const int bh  = blockIdx.y;
    const int b   = bh >> 4;
    const int h   = bh & 15;
    const int tid = threadIdx.x;
    const int qi  = blockIdx.x * 128 + tid;   // this thread's query index
    const float scale = 0.125f;               // 1/sqrt(64)

    // Load this thread's q row into packed registers
    u64 q2[32];
    {
        const float* qrow = qkv + ((size_t)(b * Tdim + qi)) * C3 + h * Ddim;
#pragma unroll
        for (int d4 = 0; d4 < 16; d4++) {
            float4 v = *reinterpret_cast<const float4*>(qrow + d4 * 4);
            q2[d4 * 2 + 0] = pk2(v.x, v.y);
            q2[d4 * 2 + 1] = pk2(v.z, v.w);
        }
    }

    float m = -1e30f, l = 0.0f;
    u64 o2[32];
#pragma unroll
    for (int d = 0; d < 32; d++) o2[d] = 0ull;

    const int nkb = blockIdx.x * 2 + 2;       // key tiles of 64 covering [0, qb*128+128)
    for (int jb = 0; jb < nkb; jb++) {
        // Cooperative load of K,V tiles [64][64]
        const float* Kbase = qkv + ((size_t)(b * Tdim + jb * 64)) * C3 + Cdim + h * Ddim;
        const float* Vbase = Kbase + Cdim;
#pragma unroll
        for (int i = 0; i < 8; i++) {
            int lin = tid + i * 128;          // 0..1023 float4 slots
            int row = lin >> 4;               // 0..63
            int c4  = lin & 15;               // 0..15
            *reinterpret_cast<float4*>(&Ks[row][c4 * 4]) =
                *reinterpret_cast<const float4*>(Kbase + (size_t)row * C3 + c4 * 4);
            *reinterpret_cast<float4*>(&Vs[row][c4 * 4]) =
                *reinterpret_cast<const float4*>(Vbase + (size_t)row * C3 + c4 * 4);
        }
        __syncthreads();

        int jmax = qi - jb * 64 + 1;          // causal: keys <= qi
        if (jmax > 64) jmax = 64;
        for (int jj = 0; jj < jmax; jj++) {
            const u64* krow = reinterpret_cast<const u64*>(&Ks[jj][0]);
            u64 s2 = 0ull;
#pragma unroll
            for (int d2 = 0; d2 < 32; d2++)
                s2 = ffma2(q2[d2], krow[d2], s2);
            float sx, sy;
            upk2(s2, sx, sy);
            float s = (sx + sy) * scale;

            if (s > m) {                       // rare after warm-up: amortized rescale
                float alpha = __expf(m - s);
                l *= alpha;
                u64 a2 = pk2(alpha, alpha);
#pragma unroll
                for (int d2 = 0; d2 < 32; d2++) o2[d2] = fmul2(o2[d2], a2);
                m = s;
            }
            float p = __expf(s - m);
            l += p;
            u64 p2 = pk2(p, p);
            const u64* vrow = reinterpret_cast<const u64*>(&Vs[jj][0]);
#pragma unroll
            for (int d2 = 0; d2 < 32; d2++)
                o2[d2] = ffma2(p2, vrow[d2], o2[d2]);
        }
        __syncthreads();
    }

    float inv = 1.0f / l;
    float* orow = out + ((size_t)(b * Tdim + qi)) * Cdim + h * Ddim;
#pragma unroll
    for (int d4 = 0; d4 < 16; d4++) {
        float x0, x1, x2, x3;
        upk2(o2[d4 * 2 + 0], x0, x1);
        upk2(o2[d4 * 2 + 1], x2, x3);
        float4 v;
        v.x = x0 * inv; v.y = x1 * inv; v.z = x2 * inv; v.w = x3 * inv;
        *reinterpret_cast<float4*>(orow + d4 * 4) = v;
    }
}

// ---------------------------------------------------------------------------
extern "C" void kernel_launch(void* const* d_in, const int* in_sizes, int n_in,
                              void* d_out, int out_size)
{
    (void)in_sizes; (void)n_in; (void)out_size;
    const float* x      = (const float*)d_in[0];
    const float* W_attn = (const float*)d_in[1];
    const float* b_attn = (const float*)d_in[2];
    const float* W_proj = (const float*)d_in[3];
    const float* b_proj = (const float*)d_in[4];
    float* out = (float*)d_out;

    float* qkv = nullptr;
    float* att = nullptr;
    cudaGetSymbolAddress((void**)&qkv, g_qkv);
    cudaGetSymbolAddress((void**)&att, g_att);

    // 1) QKV = x @ W_attn + b_attn
    {
        dim3 grid(C3 / 128, Mrows / 128);
        gemm_bias_kernel<<<grid, 256>>>(x, W_attn, b_attn, qkv, Mrows, C3, Cdim);
    }
    // 2) Causal flash attention -> att in [B,T,C]
    {
        dim3 grid(Tdim / 128, Bdim * Hdim);
        attn_kernel<<<grid, 128>>>(qkv, att);
    }
    // 3) out = att @ W_proj + b_proj
    {
        dim3 grid(Cdim / 128, Mrows / 128);
        gemm_bias_kernel<<<grid, 256>>>(att, W_proj, b_proj, out, Mrows, Cdim, Cdim);
    }
}

// round 5
// speedup vs baseline: 1.4868x; 1.4868x over previous
#include <cuda_runtime.h>
#include <cuda_bf16.h>
#include <cstdint>
#include <cstddef>

#define Bdim 4
#define Tdim 2048
#define Cdim 1024
#define Hdim 16
#define Ddim 64
#define C3   3072
#define Mrows 8192

// fp32 scratch
__device__ float g_qkv[(size_t)Mrows * C3];
__device__ float g_att[(size_t)Mrows * Cdim];
// bf16 hi/lo scratch
__device__ unsigned short g_x_hi[(size_t)Mrows * Cdim];
__device__ unsigned short g_x_lo[(size_t)Mrows * Cdim];
__device__ unsigned short g_Wa_hi[(size_t)C3 * Cdim];   // transposed [N=3072][K=1024]
__device__ unsigned short g_Wa_lo[(size_t)C3 * Cdim];
__device__ unsigned short g_Wp_hi[(size_t)Cdim * Cdim]; // transposed [N=1024][K=1024]
__device__ unsigned short g_Wp_lo[(size_t)Cdim * Cdim];
__device__ unsigned short g_ah_hi[(size_t)Mrows * Cdim];
__device__ unsigned short g_ah_lo[(size_t)Mrows * Cdim];

// ---------------------------------------------------------------------------
// mma.sync m16n8k16 bf16 (compute_103-safe tensor core path)
// ---------------------------------------------------------------------------
__device__ __forceinline__ void mma_bf16(float* d,
    uint32_t a0, uint32_t a1, uint32_t a2, uint32_t a3,
    uint32_t b0, uint32_t b1)
{
    asm volatile(
        "mma.sync.aligned.m16n8k16.row.col.f32.bf16.bf16.f32 "
        "{%0,%1,%2,%3}, {%4,%5,%6,%7}, {%8,%9}, {%0,%1,%2,%3};"
        : "+f"(d[0]), "+f"(d[1]), "+f"(d[2]), "+f"(d[3])
        : "r"(a0), "r"(a1), "r"(a2), "r"(a3), "r"(b0), "r"(b1));
}

// ---------------------------------------------------------------------------
// hi/lo split kernels
// ---------------------------------------------------------------------------
__global__ __launch_bounds__(256) void split_kernel(
    const float* __restrict__ in, unsigned short* __restrict__ hi,
    unsigned short* __restrict__ lo, int n)
{
    int i = blockIdx.x * 256 + threadIdx.x;
    if (i >= n) return;
    float x = in[i];
    __nv_bfloat16 h = __float2bfloat16(x);
    float r = x - __bfloat162float(h);
    __nv_bfloat16 l = __float2bfloat16(r);
    hi[i] = *reinterpret_cast<unsigned short*>(&h);
    lo[i] = *reinterpret_cast<unsigned short*>(&l);
}

// W [K,N] fp32 -> Wt [N,K] bf16 hi/lo (transpose + split)
__global__ __launch_bounds__(256) void splitT_kernel(
    const float* __restrict__ W, unsigned short* __restrict__ hiT,
    unsigned short* __restrict__ loT, int K, int N)
{
    __shared__ float t[32][33];
    int bn = blockIdx.x * 32;
    int bk = blockIdx.y * 32;
    int tx = threadIdx.x & 31;
    int ty = threadIdx.x >> 5;   // 0..7
#pragma unroll
    for (int i = ty; i < 32; i += 8)
        t[i][tx] = W[(size_t)(bk + i) * N + bn + tx];   // t[k_local][n_local]
    __syncthreads();
#pragma unroll
    for (int i = ty; i < 32; i += 8) {
        float x = t[tx][i];                              // k_local=tx, n_local=i
        __nv_bfloat16 h = __float2bfloat16(x);
        float r = x - __bfloat162float(h);
        __nv_bfloat16 l = __float2bfloat16(r);
        size_t o = (size_t)(bn + i) * K + bk + tx;
        hiT[o] = *reinterpret_cast<unsigned short*>(&h);
        loT[o] = *reinterpret_cast<unsigned short*>(&l);
    }
}

// ---------------------------------------------------------------------------
// GEMM via mma.sync: C[M,N] = (Ah+Al)[M,K] @ (Bh+Bl)[N,K]^T + bias[N]
// (drops Al*Bl). Block 128x128x32, 256 threads, 8 warps in 4(m)x2(n),
// warp tile 32x64 = 2x8 m16n8k16 tiles, fp32 register accumulators.
// Smem rows padded to 40 bf16 for conflict-free fragment loads.
// ---------------------------------------------------------------------------
#define BM 128
#define BN 128
#define BK 32
#define PAD 40

__global__ __launch_bounds__(256) void gemm_mma_kernel(
    const unsigned short* __restrict__ Ah, const unsigned short* __restrict__ Al,
    const unsigned short* __restrict__ Bh, const unsigned short* __restrict__ Bl,
    const float* __restrict__ bias, float* __restrict__ C,
    int M, int N, int K)
{
    __shared__ unsigned short sAh[BM][PAD];
    __shared__ unsigned short sAl[BM][PAD];
    __shared__ unsigned short sBh[BN][PAD];
    __shared__ unsigned short sBl[BN][PAD];

    const int tid = threadIdx.x;
    const int wid = tid >> 5;
    const int lane = tid & 31;
    const int g   = lane >> 2;     // group 0..7
    const int tig = lane & 3;      // thread-in-group 0..3
    const int wm  = wid & 3;       // warp m index 0..3 (32 rows each)
    const int wn  = wid >> 2;      // warp n index 0..1 (64 cols each)
    const int bm  = blockIdx.y * BM;
    const int bn  = blockIdx.x * BN;

    float acc[2][8][4];
#pragma unroll
    for (int i = 0; i < 2; i++)
#pragma unroll
        for (int j = 0; j < 8; j++)
#pragma unroll
            for (int v = 0; v < 4; v++) acc[i][j][v] = 0.0f;

    // Global-load indexing: thread t loads row t>>1, half t&1 (16 bf16 = 2 uint4)
    const int lr = tid >> 1;
    const int lh = tid & 1;

    for (int k0 = 0; k0 < K; k0 += BK) {
        {
            const unsigned short* srcA_h = Ah + (size_t)(bm + lr) * K + k0 + lh * 16;
            const unsigned short* srcA_l = Al + (size_t)(bm + lr) * K + k0 + lh * 16;
            const unsigned short* srcB_h = Bh + (size_t)(bn + lr) * K + k0 + lh * 16;
            const unsigned short* srcB_l = Bl + (size_t)(bn + lr) * K + k0 + lh * 16;
            uint4* dAh = reinterpret_cast<uint4*>(&sAh[lr][lh * 16]);
            uint4* dAl = reinterpret_cast<uint4*>(&sAl[lr][lh * 16]);
            uint4* dBh = reinterpret_cast<uint4*>(&sBh[lr][lh * 16]);
            uint4* dBl = reinterpret_cast<uint4*>(&sBl[lr][lh * 16]);
            uint4 vAh0 = reinterpret_cast<const uint4*>(srcA_h)[0];
            uint4 vAh1 = reinterpret_cast<const uint4*>(srcA_h)[1];
            uint4 vAl0 = reinterpret_cast<const uint4*>(srcA_l)[0];
            uint4 vAl1 = reinterpret_cast<const uint4*>(srcA_l)[1];
            uint4 vBh0 = reinterpret_cast<const uint4*>(srcB_h)[0];
            uint4 vBh1 = reinterpret_cast<const uint4*>(srcB_h)[1];
            uint4 vBl0 = reinterpret_cast<const uint4*>(srcB_l)[0];
            uint4 vBl1 = reinterpret_cast<const uint4*>(srcB_l)[1];
            dAh[0] = vAh0; dAh[1] = vAh1;
            dAl[0] = vAl0; dAl[1] = vAl1;
            dBh[0] = vBh0; dBh[1] = vBh1;
            dBl[0] = vBl0; dBl[1] = vBl1;
        }
        __syncthreads();

#pragma unroll
        for (int ks = 0; ks < 2; ks++) {
            const int kb = ks * 16;
            // A fragments (hi & lo) for 2 m-tiles
            uint32_t ah[2][4], al[2][4];
#pragma unroll
            for (int mt = 0; mt < 2; mt++) {
                int r0 = wm * 32 + mt * 16 + g;
                int r1 = r0 + 8;
                int c0 = kb + tig * 2;
                int c1 = c0 + 8;
                ah[mt][0] = *reinterpret_cast<const uint32_t*>(&sAh[r0][c0]);
                ah[mt][1] = *reinterpret_cast<const uint32_t*>(&sAh[r1][c0]);
                ah[mt][2] = *reinterpret_cast<const uint32_t*>(&sAh[r0][c1]);
                ah[mt][3] = *reinterpret_cast<const uint32_t*>(&sAh[r1][c1]);
                al[mt][0] = *reinterpret_cast<const uint32_t*>(&sAl[r0][c0]);
                al[mt][1] = *reinterpret_cast<const uint32_t*>(&sAl[r1][c0]);
                al[mt][2] = *reinterpret_cast<const uint32_t*>(&sAl[r0][c1]);
                al[mt][3] = *reinterpret_cast<const uint32_t*>(&sAl[r1][c1]);
            }
#pragma unroll
            for (int nt = 0; nt < 8; nt++) {
                int n = wn * 64 + nt * 8 + g;
                int c0 = kb + tig * 2;
                uint32_t bh0 = *reinterpret_cast<const uint32_t*>(&sBh[n][c0]);
                uint32_t bh1 = *reinterpret_cast<const uint32_t*>(&sBh[n][c0 + 8]);
                uint32_t bl0 = *reinterpret_cast<const uint32_t*>(&sBl[n][c0]);
                uint32_t bl1 = *reinterpret_cast<const uint32_t*>(&sBl[n][c0 + 8]);
#pragma unroll
                for (int mt = 0; mt < 2; mt++) {
                    mma_bf16(acc[mt][nt], ah[mt][0], ah[mt][1], ah[mt][2], ah[mt][3], bh0, bh1);
                    mma_bf16(acc[mt][nt], ah[mt][0], ah[mt][1], ah[mt][2], ah[mt][3], bl0, bl1);
                    mma_bf16(acc[mt][nt], al[mt][0], al[mt][1], al[mt][2], al[mt][3], bh0, bh1);
                }
            }
        }
        __syncthreads();
    }

    // Epilogue: d0,d1 at (row g, col tig*2); d2,d3 at (row g+8)
#pragma unroll
    for (int mt = 0; mt < 2; mt++) {
        int r0 = bm + wm * 32 + mt * 16 + g;
        int r1 = r0 + 8;
#pragma unroll
        for (int nt = 0; nt < 8; nt++) {
            int col = bn + wn * 64 + nt * 8 + tig * 2;
            float b0 = bias[col], b1 = bias[col + 1];
            float2 v0 = make_float2(acc[mt][nt][0] + b0, acc[mt][nt][1] + b1);
            float2 v1 = make_float2(acc[mt][nt][2] + b0, acc[mt][nt][3] + b1);
            *reinterpret_cast<float2*>(C + (size_t)r0 * N + col) = v0;
            *reinterpret_cast<float2*>(C + (size_t)r1 * N + col) = v1;
        }
    }
}

// ---------------------------------------------------------------------------
// Causal flash attention, fp32 scalar (round-1 version, known good).
// ---------------------------------------------------------------------------
__global__ __launch_bounds__(128) void attn_kernel(
    const float* __restrict__ qkv, float* __restrict__ out)
{
    __shared__ float Ks[64][64];
    __shared__ float Vs[64][64];

    const int bh  = blockIdx.y;
    const int b   = bh >> 4;
    const int h   = bh & 15;
    const int tid = threadIdx.x;
    const int qi  = blockIdx.x * 128 + tid;
    const float scale = 0.125f;

    float q[64];
    {
        const float* qrow = qkv + ((size_t)(b * Tdim + qi)) * C3 + h * Ddim;
#pragma unroll
        for (int d4 = 0; d4 < 16; d4++) {
            float4 v = *reinterpret_cast<const float4*>(qrow + d4 * 4);
            q[d4*4+0] = v.x; q[d4*4+1] = v.y; q[d4*4+2] = v.z; q[d4*4+3] = v.w;
        }
    }

    float m = -1e30f, l = 0.0f;
    float o[64];
#pragma unroll
    for (int d = 0; d < 64; d++) o[d] = 0.0f;

    const int nkb = blockIdx.x * 2 + 2;
    for (int jb = 0; jb < nkb; jb++) {
        const float* Kbase = qkv + ((size_t)(b * Tdim + jb * 64)) * C3 + Cdim + h * Ddim;
        const float* Vbase = Kbase + Cdim;
#pragma unroll
        for (int i = 0; i < 8; i++) {
            int lin = tid + i * 128;
            int row = lin >> 4;
            int c4  = lin & 15;
            *reinterpret_cast<float4*>(&Ks[row][c4 * 4]) =
                *reinterpret_cast<const float4*>(Kbase + (size_t)row * C3 + c4 * 4);
            *reinterpret_cast<float4*>(&Vs[row][c4 * 4]) =
                *reinterpret_cast<const float4*>(Vbase + (size_t)row * C3 + c4 * 4);
        }
        __syncthreads();

        int jmax = qi - jb * 64 + 1;
        if (jmax > 64) jmax = 64;
        for (int jj = 0; jj < jmax; jj++) {
            float s = 0.0f;
            const float4* krow = reinterpret_cast<const float4*>(&Ks[jj][0]);
#pragma unroll
            for (int d4 = 0; d4 < 16; d4++) {
                float4 kv = krow[d4];
                s = fmaf(q[d4*4+0], kv.x, s);
                s = fmaf(q[d4*4+1], kv.y, s);
                s = fmaf(q[d4*4+2], kv.z, s);
                s = fmaf(q[d4*4+3], kv.w, s);
            }
            s *= scale;

            if (s > m) {
                float alpha = __expf(m - s);
                l *= alpha;
#pragma unroll
                for (int d = 0; d < 64; d++) o[d] *= alpha;
                m = s;
            }
            float p = __expf(s - m);
            l += p;
            const float4* vrow = reinterpret_cast<const float4*>(&Vs[jj][0]);
#pragma unroll
            for (int d4 = 0; d4 < 16; d4++) {
                float4 vv = vrow[d4];
                o[d4*4+0] = fmaf(p, vv.x, o[d4*4+0]);
                o[d4*4+1] = fmaf(p, vv.y, o[d4*4+1]);
                o[d4*4+2] = fmaf(p, vv.z, o[d4*4+2]);
                o[d4*4+3] = fmaf(p, vv.w, o[d4*4+3]);
            }
        }
        __syncthreads();
    }

    float inv = 1.0f / l;
    float* orow = out + ((size_t)(b * Tdim + qi)) * Cdim + h * Ddim;
#pragma unroll
    for (int d4 = 0; d4 < 16; d4++) {
        float4 v;
        v.x = o[d4*4+0] * inv; v.y = o[d4*4+1] * inv;
        v.z = o[d4*4+2] * inv; v.w = o[d4*4+3] * inv;
        *reinterpret_cast<float4*>(orow + d4 * 4) = v;
    }
}

// ---------------------------------------------------------------------------
extern "C" void kernel_launch(void* const* d_in, const int* in_sizes, int n_in,
                              void* d_out, int out_size)
{
    (void)in_sizes; (void)n_in; (void)out_size;
    const float* x      = (const float*)d_in[0];
    const float* W_attn = (const float*)d_in[1];
    const float* b_attn = (const float*)d_in[2];
    const float* W_proj = (const float*)d_in[3];
    const float* b_proj = (const float*)d_in[4];
    float* out = (float*)d_out;

    float* qkv; float* att;
    unsigned short *x_hi, *x_lo, *Wa_hi, *Wa_lo, *Wp_hi, *Wp_lo, *ah_hi, *ah_lo;
    cudaGetSymbolAddress((void**)&qkv, g_qkv);
    cudaGetSymbolAddress((void**)&att, g_att);
    cudaGetSymbolAddress((void**)&x_hi, g_x_hi);
    cudaGetSymbolAddress((void**)&x_lo, g_x_lo);
    cudaGetSymbolAddress((void**)&Wa_hi, g_Wa_hi);
    cudaGetSymbolAddress((void**)&Wa_lo, g_Wa_lo);
    cudaGetSymbolAddress((void**)&Wp_hi, g_Wp_hi);
    cudaGetSymbolAddress((void**)&Wp_lo, g_Wp_lo);
    cudaGetSymbolAddress((void**)&ah_hi, g_ah_hi);
    cudaGetSymbolAddress((void**)&ah_lo, g_ah_lo);

    // Split inputs to bf16 hi/lo (weights transposed to [N,K])
    {
        int n = Mrows * Cdim;
        split_kernel<<<(n + 255) / 256, 256>>>(x, x_hi, x_lo, n);
        splitT_kernel<<<dim3(C3 / 32, Cdim / 32), 256>>>(W_attn, Wa_hi, Wa_lo, Cdim, C3);
        splitT_kernel<<<dim3(Cdim / 32, Cdim / 32), 256>>>(W_proj, Wp_hi, Wp_lo, Cdim, Cdim);
    }
    // 1) QKV = x @ W_attn + b_attn  (tensor cores via mma.sync)
    gemm_mma_kernel<<<dim3(C3 / BN, Mrows / BM), 256>>>(
        x_hi, x_lo, Wa_hi, Wa_lo, b_attn, qkv, Mrows, C3, Cdim);
    // 2) Causal flash attention (fp32)
    attn_kernel<<<dim3(Tdim / 128, Bdim * Hdim), 128>>>(qkv, att);
    // 3) split attention output, then out = att @ W_proj + b_proj
    {
        int n = Mrows * Cdim;
        split_kernel<<<(n + 255) / 256, 256>>>(att, ah_hi, ah_lo, n);
    }
    gemm_mma_kernel<<<dim3(Cdim / BN, Mrows / BM), 256>>>(
        ah_hi, ah_lo, Wp_hi, Wp_lo, b_proj, out, Mrows, Cdim, Cdim);
}

// round 8
// speedup vs baseline: 2.6092x; 1.7549x over previous
#include <cuda_runtime.h>
#include <cuda_bf16.h>
#include <cstdint>
#include <cstddef>

#define Bdim 4
#define Tdim 2048
#define Cdim 1024
#define Hdim 16
#define Ddim 64
#define C3   3072
#define Mrows 8192

// fp32 scratch
__device__ float g_qkv[(size_t)Mrows * C3];
__device__ float g_att[(size_t)Mrows * Cdim];
// bf16 hi/lo scratch
__device__ unsigned short g_x_hi[(size_t)Mrows * Cdim];
__device__ unsigned short g_x_lo[(size_t)Mrows * Cdim];
__device__ unsigned short g_Wa_hi[(size_t)C3 * Cdim];   // transposed [N=3072][K=1024]
__device__ unsigned short g_Wa_lo[(size_t)C3 * Cdim];
__device__ unsigned short g_Wp_hi[(size_t)Cdim * Cdim]; // transposed [N=1024][K=1024]
__device__ unsigned short g_Wp_lo[(size_t)Cdim * Cdim];
__device__ unsigned short g_ah_hi[(size_t)Mrows * Cdim];
__device__ unsigned short g_ah_lo[(size_t)Mrows * Cdim];
__device__ unsigned short g_qkv_hi[(size_t)Mrows * C3];
__device__ unsigned short g_qkv_lo[(size_t)Mrows * C3];

// ---------------------------------------------------------------------------
// mma.sync m16n8k16 bf16 (compute_103-safe tensor core path)
// ---------------------------------------------------------------------------
__device__ __forceinline__ void mma_bf16(float* d,
    uint32_t a0, uint32_t a1, uint32_t a2, uint32_t a3,
    uint32_t b0, uint32_t b1)
{
    asm volatile(
        "mma.sync.aligned.m16n8k16.row.col.f32.bf16.bf16.f32 "
        "{%0,%1,%2,%3}, {%4,%5,%6,%7}, {%8,%9}, {%0,%1,%2,%3};"
        : "+f"(d[0]), "+f"(d[1]), "+f"(d[2]), "+f"(d[3])
        : "r"(a0), "r"(a1), "r"(a2), "r"(a3), "r"(b0), "r"(b1));
}

__device__ __forceinline__ uint32_t bf16x2_pack(float lo, float hi) {
    uint32_t r;
    asm("cvt.rn.bf16x2.f32 %0, %1, %2;" : "=r"(r) : "f"(hi), "f"(lo));
    return r;
}
__device__ __forceinline__ float bf16_round(float x) {
    __nv_bfloat16 h = __float2bfloat16(x);
    return __bfloat162float(h);
}

// ---------------------------------------------------------------------------
// hi/lo split kernels
// ---------------------------------------------------------------------------
__global__ __launch_bounds__(256) void split_kernel(
    const float* __restrict__ in, unsigned short* __restrict__ hi,
    unsigned short* __restrict__ lo, int n)
{
    int i = blockIdx.x * 256 + threadIdx.x;
    if (i >= n) return;
    float x = in[i];
    __nv_bfloat16 h = __float2bfloat16(x);
    float r = x - __bfloat162float(h);
    __nv_bfloat16 l = __float2bfloat16(r);
    hi[i] = *reinterpret_cast<unsigned short*>(&h);
    lo[i] = *reinterpret_cast<unsigned short*>(&l);
}

// W [K,N] fp32 -> Wt [N,K] bf16 hi/lo (transpose + split)
__global__ __launch_bounds__(256) void splitT_kernel(
    const float* __restrict__ W, unsigned short* __restrict__ hiT,
    unsigned short* __restrict__ loT, int K, int N)
{
    __shared__ float t[32][33];
    int bn = blockIdx.x * 32;
    int bk = blockIdx.y * 32;
    int tx = threadIdx.x & 31;
    int ty = threadIdx.x >> 5;   // 0..7
#pragma unroll
    for (int i = ty; i < 32; i += 8)
        t[i][tx] = W[(size_t)(bk + i) * N + bn + tx];
    __syncthreads();
#pragma unroll
    for (int i = ty; i < 32; i += 8) {
        float x = t[tx][i];
        __nv_bfloat16 h = __float2bfloat16(x);
        float r = x - __bfloat162float(h);
        __nv_bfloat16 l = __float2bfloat16(r);
        size_t o = (size_t)(bn + i) * K + bk + tx;
        hiT[o] = *reinterpret_cast<unsigned short*>(&h);
        loT[o] = *reinterpret_cast<unsigned short*>(&l);
    }
}

// ---------------------------------------------------------------------------
// GEMM via mma.sync (validated round 5) + 2 CTAs/SM
// ---------------------------------------------------------------------------
#define BM 128
#define BN 128
#define BK 32
#define PAD 40

__global__ __launch_bounds__(256, 2) void gemm_mma_kernel(
    const unsigned short* __restrict__ Ah, const unsigned short* __restrict__ Al,
    const unsigned short* __restrict__ Bh, const unsigned short* __restrict__ Bl,
    const float* __restrict__ bias, float* __restrict__ C,
    int M, int N, int K)
{
    __shared__ unsigned short sAh[BM][PAD];
    __shared__ unsigned short sAl[BM][PAD];
    __shared__ unsigned short sBh[BN][PAD];
    __shared__ unsigned short sBl[BN][PAD];

    const int tid = threadIdx.x;
    const int wid = tid >> 5;
    const int lane = tid & 31;
    const int g   = lane >> 2;
    const int tig = lane & 3;
    const int wm  = wid & 3;
    const int wn  = wid >> 2;
    const int bm  = blockIdx.y * BM;
    const int bn  = blockIdx.x * BN;

    float acc[2][8][4];
#pragma unroll
    for (int i = 0; i < 2; i++)
#pragma unroll
        for (int j = 0; j < 8; j++)
#pragma unroll
            for (int v = 0; v < 4; v++) acc[i][j][v] = 0.0f;

    const int lr = tid >> 1;
    const int lh = tid & 1;

    for (int k0 = 0; k0 < K; k0 += BK) {
        {
            const unsigned short* srcA_h = Ah + (size_t)(bm + lr) * K + k0 + lh * 16;
            const unsigned short* srcA_l = Al + (size_t)(bm + lr) * K + k0 + lh * 16;
            const unsigned short* srcB_h = Bh + (size_t)(bn + lr) * K + k0 + lh * 16;
            const unsigned short* srcB_l = Bl + (size_t)(bn + lr) * K + k0 + lh * 16;
            uint4* dAh = reinterpret_cast<uint4*>(&sAh[lr][lh * 16]);
            uint4* dAl = reinterpret_cast<uint4*>(&sAl[lr][lh * 16]);
            uint4* dBh = reinterpret_cast<uint4*>(&sBh[lr][lh * 16]);
            uint4* dBl = reinterpret_cast<uint4*>(&sBl[lr][lh * 16]);
            uint4 vAh0 = reinterpret_cast<const uint4*>(srcA_h)[0];
            uint4 vAh1 = reinterpret_cast<const uint4*>(srcA_h)[1];
            uint4 vAl0 = reinterpret_cast<const uint4*>(srcA_l)[0];
            uint4 vAl1 = reinterpret_cast<const uint4*>(srcA_l)[1];
            uint4 vBh0 = reinterpret_cast<const uint4*>(srcB_h)[0];
            uint4 vBh1 = reinterpret_cast<const uint4*>(srcB_h)[1];
            uint4 vBl0 = reinterpret_cast<const uint4*>(srcB_l)[0];
            uint4 vBl1 = reinterpret_cast<const uint4*>(srcB_l)[1];
            dAh[0] = vAh0; dAh[1] = vAh1;
            dAl[0] = vAl0; dAl[1] = vAl1;
            dBh[0] = vBh0; dBh[1] = vBh1;
            dBl[0] = vBl0; dBl[1] = vBl1;
        }
        __syncthreads();

#pragma unroll
        for (int ks = 0; ks < 2; ks++) {
            const int kb = ks * 16;
            uint32_t ah[2][4], al[2][4];
#pragma unroll
            for (int mt = 0; mt < 2; mt++) {
                int r0 = wm * 32 + mt * 16 + g;
                int r1 = r0 + 8;
                int c0 = kb + tig * 2;
                int c1 = c0 + 8;
                ah[mt][0] = *reinterpret_cast<const uint32_t*>(&sAh[r0][c0]);
                ah[mt][1] = *reinterpret_cast<const uint32_t*>(&sAh[r1][c0]);
                ah[mt][2] = *reinterpret_cast<const uint32_t*>(&sAh[r0][c1]);
                ah[mt][3] = *reinterpret_cast<const uint32_t*>(&sAh[r1][c1]);
                al[mt][0] = *reinterpret_cast<const uint32_t*>(&sAl[r0][c0]);
                al[mt][1] = *reinterpret_cast<const uint32_t*>(&sAl[r1][c0]);
                al[mt][2] = *reinterpret_cast<const uint32_t*>(&sAl[r0][c1]);
                al[mt][3] = *reinterpret_cast<const uint32_t*>(&sAl[r1][c1]);
            }
#pragma unroll
            for (int nt = 0; nt < 8; nt++) {
                int n = wn * 64 + nt * 8 + g;
                int c0 = kb + tig * 2;
                uint32_t bh0 = *reinterpret_cast<const uint32_t*>(&sBh[n][c0]);
                uint32_t bh1 = *reinterpret_cast<const uint32_t*>(&sBh[n][c0 + 8]);
                uint32_t bl0 = *reinterpret_cast<const uint32_t*>(&sBl[n][c0]);
                uint32_t bl1 = *reinterpret_cast<const uint32_t*>(&sBl[n][c0 + 8]);
#pragma unroll
                for (int mt = 0; mt < 2; mt++) {
                    mma_bf16(acc[mt][nt], ah[mt][0], ah[mt][1], ah[mt][2], ah[mt][3], bh0, bh1);
                    mma_bf16(acc[mt][nt], ah[mt][0], ah[mt][1], ah[mt][2], ah[mt][3], bl0, bl1);
                    mma_bf16(acc[mt][nt], al[mt][0], al[mt][1], al[mt][2], al[mt][3], bh0, bh1);
                }
            }
        }
        __syncthreads();
    }

#pragma unroll
    for (int mt = 0; mt < 2; mt++) {
        int r0 = bm + wm * 32 + mt * 16 + g;
        int r1 = r0 + 8;
#pragma unroll
        for (int nt = 0; nt < 8; nt++) {
            int col = bn + wn * 64 + nt * 8 + tig * 2;
            float b0 = bias[col], b1 = bias[col + 1];
            float2 v0 = make_float2(acc[mt][nt][0] + b0, acc[mt][nt][1] + b1);
            float2 v1 = make_float2(acc[mt][nt][2] + b0, acc[mt][nt][3] + b1);
            *reinterpret_cast<float2*>(C + (size_t)r0 * N + col) = v0;
            *reinterpret_cast<float2*>(C + (size_t)r1 * N + col) = v1;
        }
    }
}

// ---------------------------------------------------------------------------
// Tensor-core causal flash attention.
// Grid (T/64, B*H), 128 threads = 4 warps; warp w owns q rows [w*16, w*16+16).
// S = Qh*Kh + Qh*Kl + Ql*Kh (fp32 acc).
// P split hi/lo: O += Ph*Vh + Ph*Vl + Pl*Vh; l accumulated from (p_hi + p_lo)
// so numerator and denominator agree to ~2^-17.
// V stored transposed in smem ([d][k]); Q smem aliased into K buffers.
// ---------------------------------------------------------------------------
#define APAD 72

__global__ __launch_bounds__(128) void attn_mma_kernel(
    const unsigned short* __restrict__ qvh, const unsigned short* __restrict__ qvl,
    float* __restrict__ out)
{
    __shared__ __align__(16) unsigned short sKh[64][APAD], sKl[64][APAD];  // Q first, then K
    __shared__ __align__(16) unsigned short sVh[64][APAD], sVl[64][APAD];

    const int tid = threadIdx.x;
    const int w = tid >> 5, lane = tid & 31;
    const int g = lane >> 2, tig = lane & 3;
    const int bh = blockIdx.y, b = bh >> 4, h = bh & 15;
    const int qt = blockIdx.x, q0 = qt * 64;

    // Load Q hi/lo tile (64 rows x 64 bf16) into the K buffers
    {
        int row = tid >> 1, half = tid & 1;
        size_t go = ((size_t)(b * Tdim + q0 + row)) * C3 + h * Ddim + half * 32;
        const uint4* gh = reinterpret_cast<const uint4*>(qvh + go);
        const uint4* gl = reinterpret_cast<const uint4*>(qvl + go);
        uint4* dh = reinterpret_cast<uint4*>(&sKh[row][half * 32]);
        uint4* dl = reinterpret_cast<uint4*>(&sKl[row][half * 32]);
#pragma unroll
        for (int i = 0; i < 4; i++) { dh[i] = gh[i]; dl[i] = gl[i]; }
    }
    __syncthreads();

    // Hoist Q fragments (4 k-chunks); Q smem is dead afterwards
    uint32_t aqh[4][4], aql[4][4];
    {
        int r0 = w * 16 + g, r1 = r0 + 8;
#pragma unroll
        for (int kk = 0; kk < 4; kk++) {
            int c0 = kk * 16 + tig * 2, c1 = c0 + 8;
            aqh[kk][0] = *reinterpret_cast<const uint32_t*>(&sKh[r0][c0]);
            aqh[kk][1] = *reinterpret_cast<const uint32_t*>(&sKh[r1][c0]);
            aqh[kk][2] = *reinterpret_cast<const uint32_t*>(&sKh[r0][c1]);
            aqh[kk][3] = *reinterpret_cast<const uint32_t*>(&sKh[r1][c1]);
            aql[kk][0] = *reinterpret_cast<const uint32_t*>(&sKl[r0][c0]);
            aql[kk][1] = *reinterpret_cast<const uint32_t*>(&sKl[r1][c0]);
            aql[kk][2] = *reinterpret_cast<const uint32_t*>(&sKl[r0][c1]);
            aql[kk][3] = *reinterpret_cast<const uint32_t*>(&sKl[r1][c1]);
        }
    }

    float m0 = -1e30f, m1 = -1e30f, l0 = 0.0f, l1 = 0.0f;
    float O[8][4];
#pragma unroll
    for (int dt = 0; dt < 8; dt++)
#pragma unroll
        for (int v = 0; v < 4; v++) O[dt][v] = 0.0f;

    for (int jb = 0; jb <= qt; jb++) {
        __syncthreads();   // previous iteration's readers done (also covers Q hoist)
        // Load K hi/lo
        {
            int row = tid >> 1, half = tid & 1;
            size_t go = ((size_t)(b * Tdim + jb * 64 + row)) * C3 + Cdim + h * Ddim + half * 32;
            const uint4* gh = reinterpret_cast<const uint4*>(qvh + go);
            const uint4* gl = reinterpret_cast<const uint4*>(qvl + go);
            uint4* dh = reinterpret_cast<uint4*>(&sKh[row][half * 32]);
            uint4* dl = reinterpret_cast<uint4*>(&sKl[row][half * 32]);
#pragma unroll
            for (int i = 0; i < 4; i++) { dh[i] = gh[i]; dl[i] = gl[i]; }
        }
        // Load V transposed: sV[d][k]
        {
            int k = tid >> 1, dbase = (tid & 1) * 32;
            size_t go = ((size_t)(b * Tdim + jb * 64 + k)) * C3 + 2 * Cdim + h * Ddim + dbase;
            uint4 hv[4], lv[4];
#pragma unroll
            for (int i = 0; i < 4; i++) {
                hv[i] = reinterpret_cast<const uint4*>(qvh + go)[i];
                lv[i] = reinterpret_cast<const uint4*>(qvl + go)[i];
            }
#pragma unroll
            for (int i = 0; i < 4; i++) {
                const unsigned short* ph = reinterpret_cast<const unsigned short*>(&hv[i]);
                const unsigned short* pl = reinterpret_cast<const unsigned short*>(&lv[i]);
#pragma unroll
                for (int e = 0; e < 8; e++) {
                    sVh[dbase + i * 8 + e][k] = ph[e];
                    sVl[dbase + i * 8 + e][k] = pl[e];
                }
            }
        }
        __syncthreads();

        // S = Q K^T (3 passes)
        float S[8][4];
#pragma unroll
        for (int nt = 0; nt < 8; nt++)
#pragma unroll
            for (int v = 0; v < 4; v++) S[nt][v] = 0.0f;
#pragma unroll
        for (int kk = 0; kk < 4; kk++) {
            int c0 = kk * 16 + tig * 2, c1 = c0 + 8;
#pragma unroll
            for (int nt = 0; nt < 8; nt++) {
                int n = nt * 8 + g;
                uint32_t kh0 = *reinterpret_cast<const uint32_t*>(&sKh[n][c0]);
                uint32_t kh1 = *reinterpret_cast<const uint32_t*>(&sKh[n][c1]);
                uint32_t kl0 = *reinterpret_cast<const uint32_t*>(&sKl[n][c0]);
                uint32_t kl1 = *reinterpret_cast<const uint32_t*>(&sKl[n][c1]);
                mma_bf16(S[nt], aqh[kk][0], aqh[kk][1], aqh[kk][2], aqh[kk][3], kh0, kh1);
                mma_bf16(S[nt], aqh[kk][0], aqh[kk][1], aqh[kk][2], aqh[kk][3], kl0, kl1);
                mma_bf16(S[nt], aql[kk][0], aql[kk][1], aql[kk][2], aql[kk][3], kh0, kh1);
            }
        }

        // Scale + causal mask (only diagonal tile needs masking)
        const int lq0 = w * 16 + g, lq1 = lq0 + 8;
#pragma unroll
        for (int nt = 0; nt < 8; nt++) {
            int lj = nt * 8 + tig * 2;
            S[nt][0] *= 0.125f; S[nt][1] *= 0.125f;
            S[nt][2] *= 0.125f; S[nt][3] *= 0.125f;
            if (jb == qt) {
                if (lj     > lq0) S[nt][0] = -1e30f;
                if (lj + 1 > lq0) S[nt][1] = -1e30f;
                if (lj     > lq1) S[nt][2] = -1e30f;
                if (lj + 1 > lq1) S[nt][3] = -1e30f;
            }
        }

        // Online softmax (rows g / g+8, stats replicated across the lane quad)
        float tm0 = -1e30f, tm1 = -1e30f;
#pragma unroll
        for (int nt = 0; nt < 8; nt++) {
            tm0 = fmaxf(tm0, fmaxf(S[nt][0], S[nt][1]));
            tm1 = fmaxf(tm1, fmaxf(S[nt][2], S[nt][3]));
        }
        tm0 = fmaxf(tm0, __shfl_xor_sync(0xffffffffu, tm0, 1));
        tm0 = fmaxf(tm0, __shfl_xor_sync(0xffffffffu, tm0, 2));
        tm1 = fmaxf(tm1, __shfl_xor_sync(0xffffffffu, tm1, 1));
        tm1 = fmaxf(tm1, __shfl_xor_sync(0xffffffffu, tm1, 2));
        float mn0 = fmaxf(m0, tm0), mn1 = fmaxf(m1, tm1);
        float al0 = __expf(m0 - mn0), al1 = __expf(m1 - mn1);
        m0 = mn0; m1 = mn1;
        l0 *= al0; l1 *= al1;
#pragma unroll
        for (int dt = 0; dt < 8; dt++) {
            O[dt][0] *= al0; O[dt][1] *= al0;
            O[dt][2] *= al1; O[dt][3] *= al1;
        }

        // P hi/lo split; l accumulates (p_hi + p_lo) for num/denom consistency
        float rs0 = 0.0f, rs1 = 0.0f;
        uint32_t aPh[4][4], aPl[4][4];
#pragma unroll
        for (int nt = 0; nt < 8; nt++) {
            float p0 = __expf(S[nt][0] - m0);
            float p1 = __expf(S[nt][1] - m0);
            float p2 = __expf(S[nt][2] - m1);
            float p3 = __expf(S[nt][3] - m1);
            float p0h = bf16_round(p0), p1h = bf16_round(p1);
            float p2h = bf16_round(p2), p3h = bf16_round(p3);
            float p0l = bf16_round(p0 - p0h), p1l = bf16_round(p1 - p1h);
            float p2l = bf16_round(p2 - p2h), p3l = bf16_round(p3 - p3h);
            rs0 += (p0h + p0l) + (p1h + p1l);
            rs1 += (p2h + p2l) + (p3h + p3l);
            int kk = nt >> 1, hf = (nt & 1) * 2;
            aPh[kk][hf + 0] = bf16x2_pack(p0h, p1h);
            aPh[kk][hf + 1] = bf16x2_pack(p2h, p3h);
            aPl[kk][hf + 0] = bf16x2_pack(p0l, p1l);
            aPl[kk][hf + 1] = bf16x2_pack(p2l, p3l);
        }
        rs0 += __shfl_xor_sync(0xffffffffu, rs0, 1);
        rs0 += __shfl_xor_sync(0xffffffffu, rs0, 2);
        rs1 += __shfl_xor_sync(0xffffffffu, rs1, 1);
        rs1 += __shfl_xor_sync(0xffffffffu, rs1, 2);
        l0 += rs0; l1 += rs1;

        // O += Ph*Vh + Ph*Vl + Pl*Vh
#pragma unroll
        for (int kk = 0; kk < 4; kk++) {
            int c0 = kk * 16 + tig * 2, c1 = c0 + 8;
#pragma unroll
            for (int dt = 0; dt < 8; dt++) {
                int n = dt * 8 + g;
                uint32_t vh0 = *reinterpret_cast<const uint32_t*>(&sVh[n][c0]);
                uint32_t vh1 = *reinterpret_cast<const uint32_t*>(&sVh[n][c1]);
                uint32_t vl0 = *reinterpret_cast<const uint32_t*>(&sVl[n][c0]);
                uint32_t vl1 = *reinterpret_cast<const uint32_t*>(&sVl[n][c1]);
                mma_bf16(O[dt], aPh[kk][0], aPh[kk][1], aPh[kk][2], aPh[kk][3], vh0, vh1);
                mma_bf16(O[dt], aPh[kk][0], aPh[kk][1], aPh[kk][2], aPh[kk][3], vl0, vl1);
                mma_bf16(O[dt], aPl[kk][0], aPl[kk][1], aPl[kk][2], aPl[kk][3], vh0, vh1);
            }
        }
    }

    // Epilogue
    float inv0 = 1.0f / l0, inv1 = 1.0f / l1;
    int r0 = q0 + w * 16 + g, r1 = r0 + 8;
    float* o0 = out + ((size_t)(b * Tdim + r0)) * Cdim + h * Ddim;
    float* o1 = out + ((size_t)(b * Tdim + r1)) * Cdim + h * Ddim;
#pragma unroll
    for (int dt = 0; dt < 8; dt++) {
        int d = dt * 8 + tig * 2;
        *reinterpret_cast<float2*>(o0 + d) = make_float2(O[dt][0] * inv0, O[dt][1] * inv0);
        *reinterpret_cast<float2*>(o1 + d) = make_float2(O[dt][2] * inv1, O[dt][3] * inv1);
    }
}

// ---------------------------------------------------------------------------
extern "C" void kernel_launch(void* const* d_in, const int* in_sizes, int n_in,
                              void* d_out, int out_size)
{
    (void)in_sizes; (void)n_in; (void)out_size;
    const float* x      = (const float*)d_in[0];
    const float* W_attn = (const float*)d_in[1];
    const float* b_attn = (const float*)d_in[2];
    const float* W_proj = (const float*)d_in[3];
    const float* b_proj = (const float*)d_in[4];
    float* out = (float*)d_out;

    float* qkv; float* att;
    unsigned short *x_hi, *x_lo, *Wa_hi, *Wa_lo, *Wp_hi, *Wp_lo, *ah_hi, *ah_lo, *qkv_hi, *qkv_lo;
    cudaGetSymbolAddress((void**)&qkv, g_qkv);
    cudaGetSymbolAddress((void**)&att, g_att);
    cudaGetSymbolAddress((void**)&x_hi, g_x_hi);
    cudaGetSymbolAddress((void**)&x_lo, g_x_lo);
    cudaGetSymbolAddress((void**)&Wa_hi, g_Wa_hi);
    cudaGetSymbolAddress((void**)&Wa_lo, g_Wa_lo);
    cudaGetSymbolAddress((void**)&Wp_hi, g_Wp_hi);
    cudaGetSymbolAddress((void**)&Wp_lo, g_Wp_lo);
    cudaGetSymbolAddress((void**)&ah_hi, g_ah_hi);
    cudaGetSymbolAddress((void**)&ah_lo, g_ah_lo);
    cudaGetSymbolAddress((void**)&qkv_hi, g_qkv_hi);
    cudaGetSymbolAddress((void**)&qkv_lo, g_qkv_lo);

    // Split inputs to bf16 hi/lo (weights transposed to [N,K])
    {
        int n = Mrows * Cdim;
        split_kernel<<<(n + 255) / 256, 256>>>(x, x_hi, x_lo, n);
        splitT_kernel<<<dim3(C3 / 32, Cdim / 32), 256>>>(W_attn, Wa_hi, Wa_lo, Cdim, C3);
        splitT_kernel<<<dim3(Cdim / 32, Cdim / 32), 256>>>(W_proj, Wp_hi, Wp_lo, Cdim, Cdim);
    }
    // 1) QKV = x @ W_attn + b_attn
    gemm_mma_kernel<<<dim3(C3 / BN, Mrows / BM), 256>>>(
        x_hi, x_lo, Wa_hi, Wa_lo, b_attn, qkv, Mrows, C3, Cdim);
    // 2) Split qkv to bf16 hi/lo, then tensor-core flash attention
    {
        int n = Mrows * C3;
        split_kernel<<<(n + 255) / 256, 256>>>(qkv, qkv_hi, qkv_lo, n);
    }
    attn_mma_kernel<<<dim3(Tdim / 64, Bdim * Hdim), 128>>>(qkv_hi, qkv_lo, att);
    // 3) Split attention output, then out = att @ W_proj + b_proj
    {
        int n = Mrows * Cdim;
        split_kernel<<<(n + 255) / 256, 256>>>(att, ah_hi, ah_lo, n);
    }
    gemm_mma_kernel<<<dim3(Cdim / BN, Mrows / BM), 256>>>(
        ah_hi, ah_lo, Wp_hi, Wp_lo, b_proj, out, Mrows, Cdim, Cdim);
}

// round 9
// speedup vs baseline: 2.9934x; 1.1472x over previous
#include <cuda_runtime.h>
#include <cuda_bf16.h>
#include <cstdint>
#include <cstddef>

#define Bdim 4
#define Tdim 2048
#define Cdim 1024
#define Hdim 16
#define Ddim 64
#define C3   3072
#define Mrows 8192

// bf16 hi/lo scratch
__device__ unsigned short g_x_hi[(size_t)Mrows * Cdim];
__device__ unsigned short g_x_lo[(size_t)Mrows * Cdim];
__device__ unsigned short g_Wa_hi[(size_t)C3 * Cdim];   // transposed [N=3072][K=1024]
__device__ unsigned short g_Wa_lo[(size_t)C3 * Cdim];
__device__ unsigned short g_Wp_hi[(size_t)Cdim * Cdim]; // transposed [N=1024][K=1024]
__device__ unsigned short g_Wp_lo[(size_t)Cdim * Cdim];
__device__ unsigned short g_ah_hi[(size_t)Mrows * Cdim];
__device__ unsigned short g_ah_lo[(size_t)Mrows * Cdim];
__device__ unsigned short g_qkv_hi[(size_t)Mrows * C3];
__device__ unsigned short g_qkv_lo[(size_t)Mrows * C3];

// ---------------------------------------------------------------------------
// mma.sync m16n8k16 bf16 + cp.async helpers (compute_103-safe)
// ---------------------------------------------------------------------------
__device__ __forceinline__ void mma_bf16(float* d,
    uint32_t a0, uint32_t a1, uint32_t a2, uint32_t a3,
    uint32_t b0, uint32_t b1)
{
    asm volatile(
        "mma.sync.aligned.m16n8k16.row.col.f32.bf16.bf16.f32 "
        "{%0,%1,%2,%3}, {%4,%5,%6,%7}, {%8,%9}, {%0,%1,%2,%3};"
        : "+f"(d[0]), "+f"(d[1]), "+f"(d[2]), "+f"(d[3])
        : "r"(a0), "r"(a1), "r"(a2), "r"(a3), "r"(b0), "r"(b1));
}

__device__ __forceinline__ uint32_t bf16x2_pack(float lo, float hi) {
    uint32_t r;
    asm("cvt.rn.bf16x2.f32 %0, %1, %2;" : "=r"(r) : "f"(hi), "f"(lo));
    return r;
}
__device__ __forceinline__ float bf16_round(float x) {
    __nv_bfloat16 h = __float2bfloat16(x);
    return __bfloat162float(h);
}
__device__ __forceinline__ void cp_async16(void* smem_dst, const void* gsrc) {
    uint32_t sa = (uint32_t)__cvta_generic_to_shared(smem_dst);
    asm volatile("cp.async.cg.shared.global [%0], [%1], 16;" :: "r"(sa), "l"(gsrc) : "memory");
}
__device__ __forceinline__ void cp_async_commit() {
    asm volatile("cp.async.commit_group;" ::: "memory");
}
template<int N> __device__ __forceinline__ void cp_async_wait() {
    asm volatile("cp.async.wait_group %0;" :: "n"(N) : "memory");
}

// ---------------------------------------------------------------------------
// hi/lo split kernels (inputs only; intermediate splits are fused)
// ---------------------------------------------------------------------------
__global__ __launch_bounds__(256) void split_kernel(
    const float* __restrict__ in, unsigned short* __restrict__ hi,
    unsigned short* __restrict__ lo, int n)
{
    int i = blockIdx.x * 256 + threadIdx.x;
    if (i >= n) return;
    float x = in[i];
    __nv_bfloat16 h = __float2bfloat16(x);
    float r = x - __bfloat162float(h);
    __nv_bfloat16 l = __float2bfloat16(r);
    hi[i] = *reinterpret_cast<unsigned short*>(&h);
    lo[i] = *reinterpret_cast<unsigned short*>(&l);
}

__global__ __launch_bounds__(256) void splitT_kernel(
    const float* __restrict__ W, unsigned short* __restrict__ hiT,
    unsigned short* __restrict__ loT, int K, int N)
{
    __shared__ float t[32][33];
    int bn = blockIdx.x * 32;
    int bk = blockIdx.y * 32;
    int tx = threadIdx.x & 31;
    int ty = threadIdx.x >> 5;
#pragma unroll
    for (int i = ty; i < 32; i += 8)
        t[i][tx] = W[(size_t)(bk + i) * N + bn + tx];
    __syncthreads();
#pragma unroll
    for (int i = ty; i < 32; i += 8) {
        float x = t[tx][i];
        __nv_bfloat16 h = __float2bfloat16(x);
        float r = x - __bfloat162float(h);
        __nv_bfloat16 l = __float2bfloat16(r);
        size_t o = (size_t)(bn + i) * K + bk + tx;
        hiT[o] = *reinterpret_cast<unsigned short*>(&h);
        loT[o] = *reinterpret_cast<unsigned short*>(&l);
    }
}

// ---------------------------------------------------------------------------
// GEMM via mma.sync with cp.async double-buffered mainloop.
// C = (Ah+Al) @ (Bh+Bl)^T + bias (drops Al*Bl).
// Epilogue: fp32 out (C) OR fused bf16 hi/lo split (OHi/OLo).
// Dynamic smem: 2 buffers x 4 tiles x 128 x PAD shorts = 81920 B.
// ---------------------------------------------------------------------------
#define BM 128
#define BN 128
#define BK 32
#define PAD 40
#define GTILE (128 * PAD)          // shorts per tile
#define GBUF  (4 * GTILE)          // shorts per buffer
#define GEMM_SMEM_BYTES (2 * GBUF * 2)

__global__ __launch_bounds__(256, 2) void gemm_mma_kernel(
    const unsigned short* __restrict__ Ah, const unsigned short* __restrict__ Al,
    const unsigned short* __restrict__ Bh, const unsigned short* __restrict__ Bl,
    const float* __restrict__ bias, float* __restrict__ C,
    unsigned short* __restrict__ OHi, unsigned short* __restrict__ OLo,
    int M, int N, int K)
{
    extern __shared__ unsigned short sm[];

    const int tid = threadIdx.x;
    const int wid = tid >> 5;
    const int lane = tid & 31;
    const int g   = lane >> 2;
    const int tig = lane & 3;
    const int wm  = wid & 3;
    const int wn  = wid >> 2;
    const int bm  = blockIdx.y * BM;
    const int bn  = blockIdx.x * BN;

    float acc[2][8][4];
#pragma unroll
    for (int i = 0; i < 2; i++)
#pragma unroll
        for (int j = 0; j < 8; j++)
#pragma unroll
            for (int v = 0; v < 4; v++) acc[i][j][v] = 0.0f;

    const int lr = tid >> 1;       // row 0..127
    const int lh = tid & 1;        // 16-short half

    const int nk = K / BK;

    // async load of K-chunk s into buffer buf (8x cp.async 16B per thread)
    auto load_tile = [&](int s, int buf) {
        const int k0 = s * BK;
        unsigned short* base = sm + buf * GBUF + lr * PAD + lh * 16;
        const size_t aoff = (size_t)(bm + lr) * K + k0 + lh * 16;
        const size_t boff = (size_t)(bn + lr) * K + k0 + lh * 16;
        cp_async16(base + 0 * GTILE,     Ah + aoff);
        cp_async16(base + 0 * GTILE + 8, Ah + aoff + 8);
        cp_async16(base + 1 * GTILE,     Al + aoff);
        cp_async16(base + 1 * GTILE + 8, Al + aoff + 8);
        cp_async16(base + 2 * GTILE,     Bh + boff);
        cp_async16(base + 2 * GTILE + 8, Bh + boff + 8);
        cp_async16(base + 3 * GTILE,     Bl + boff);
        cp_async16(base + 3 * GTILE + 8, Bl + boff + 8);
    };

    load_tile(0, 0);
    cp_async_commit();

    for (int s = 0; s < nk; s++) {
        if (s + 1 < nk) {
            load_tile(s + 1, (s + 1) & 1);
            cp_async_commit();
            cp_async_wait<1>();
        } else {
            cp_async_wait<0>();
        }
        __syncthreads();

        const unsigned short* pAh = sm + (s & 1) * GBUF;
        const unsigned short* pAl = pAh + GTILE;
        const unsigned short* pBh = pAl + GTILE;
        const unsigned short* pBl = pBh + GTILE;

#pragma unroll
        for (int ks = 0; ks < 2; ks++) {
            const int kb = ks * 16;
            uint32_t ah[2][4], al[2][4];
#pragma unroll
            for (int mt = 0; mt < 2; mt++) {
                int r0 = (wm * 32 + mt * 16 + g) * PAD;
                int r1 = r0 + 8 * PAD;
                int c0 = kb + tig * 2;
                int c1 = c0 + 8;
                ah[mt][0] = *reinterpret_cast<const uint32_t*>(pAh + r0 + c0);
                ah[mt][1] = *reinterpret_cast<const uint32_t*>(pAh + r1 + c0);
                ah[mt][2] = *reinterpret_cast<const uint32_t*>(pAh + r0 + c1);
                ah[mt][3] = *reinterpret_cast<const uint32_t*>(pAh + r1 + c1);
                al[mt][0] = *reinterpret_cast<const uint32_t*>(pAl + r0 + c0);
                al[mt][1] = *reinterpret_cast<const uint32_t*>(pAl + r1 + c0);
                al[mt][2] = *reinterpret_cast<const uint32_t*>(pAl + r0 + c1);
                al[mt][3] = *reinterpret_cast<const uint32_t*>(pAl + r1 + c1);
            }
#pragma unroll
            for (int nt = 0; nt < 8; nt++) {
                int n = (wn * 64 + nt * 8 + g) * PAD;
                int c0 = kb + tig * 2;
                uint32_t bh0 = *reinterpret_cast<const uint32_t*>(pBh + n + c0);
                uint32_t bh1 = *reinterpret_cast<const uint32_t*>(pBh + n + c0 + 8);
                uint32_t bl0 = *reinterpret_cast<const uint32_t*>(pBl + n + c0);
                uint32_t bl1 = *reinterpret_cast<const uint32_t*>(pBl + n + c0 + 8);
#pragma unroll
                for (int mt = 0; mt < 2; mt++) {
                    mma_bf16(acc[mt][nt], ah[mt][0], ah[mt][1], ah[mt][2], ah[mt][3], bh0, bh1);
                    mma_bf16(acc[mt][nt], ah[mt][0], ah[mt][1], ah[mt][2], ah[mt][3], bl0, bl1);
                    mma_bf16(acc[mt][nt], al[mt][0], al[mt][1], al[mt][2], al[mt][3], bh0, bh1);
                }
            }
        }
        __syncthreads();
    }

    // Epilogue
#pragma unroll
    for (int mt = 0; mt < 2; mt++) {
        int r0 = bm + wm * 32 + mt * 16 + g;
        int r1 = r0 + 8;
#pragma unroll
        for (int nt = 0; nt < 8; nt++) {
            int col = bn + wn * 64 + nt * 8 + tig * 2;
            float b0 = bias[col], b1 = bias[col + 1];
            float v00 = acc[mt][nt][0] + b0, v01 = acc[mt][nt][1] + b1;
            float v10 = acc[mt][nt][2] + b0, v11 = acc[mt][nt][3] + b1;
            if (C) {
                *reinterpret_cast<float2*>(C + (size_t)r0 * N + col) = make_float2(v00, v01);
                *reinterpret_cast<float2*>(C + (size_t)r1 * N + col) = make_float2(v10, v11);
            } else {
                float h00 = bf16_round(v00), h01 = bf16_round(v01);
                float h10 = bf16_round(v10), h11 = bf16_round(v11);
                *reinterpret_cast<uint32_t*>(OHi + (size_t)r0 * N + col) = bf16x2_pack(h00, h01);
                *reinterpret_cast<uint32_t*>(OHi + (size_t)r1 * N + col) = bf16x2_pack(h10, h11);
                *reinterpret_cast<uint32_t*>(OLo + (size_t)r0 * N + col) = bf16x2_pack(v00 - h00, v01 - h01);
                *reinterpret_cast<uint32_t*>(OLo + (size_t)r1 * N + col) = bf16x2_pack(v10 - h10, v11 - h11);
            }
        }
    }
}

// ---------------------------------------------------------------------------
// Tensor-core causal flash attention (validated round 8).
// Epilogue now emits bf16 hi/lo directly (fused split).
// ---------------------------------------------------------------------------
#define APAD 72

__global__ __launch_bounds__(128) void attn_mma_kernel(
    const unsigned short* __restrict__ qvh, const unsigned short* __restrict__ qvl,
    unsigned short* __restrict__ outHi, unsigned short* __restrict__ outLo)
{
    __shared__ __align__(16) unsigned short sKh[64][APAD], sKl[64][APAD];  // Q first, then K
    __shared__ __align__(16) unsigned short sVh[64][APAD], sVl[64][APAD];

    const int tid = threadIdx.x;
    const int w = tid >> 5, lane = tid & 31;
    const int g = lane >> 2, tig = lane & 3;
    const int bh = blockIdx.y, b = bh >> 4, h = bh & 15;
    const int qt = blockIdx.x, q0 = qt * 64;

    // Load Q hi/lo tile (64 x 64) into the K buffers
    {
        int row = tid >> 1, half = tid & 1;
        size_t go = ((size_t)(b * Tdim + q0 + row)) * C3 + h * Ddim + half * 32;
        const uint4* gh = reinterpret_cast<const uint4*>(qvh + go);
        const uint4* gl = reinterpret_cast<const uint4*>(qvl + go);
        uint4* dh = reinterpret_cast<uint4*>(&sKh[row][half * 32]);
        uint4* dl = reinterpret_cast<uint4*>(&sKl[row][half * 32]);
#pragma unroll
        for (int i = 0; i < 4; i++) { dh[i] = gh[i]; dl[i] = gl[i]; }
    }
    __syncthreads();

    // Hoist Q fragments; Q smem dead afterwards
    uint32_t aqh[4][4], aql[4][4];
    {
        int r0 = w * 16 + g, r1 = r0 + 8;
#pragma unroll
        for (int kk = 0; kk < 4; kk++) {
            int c0 = kk * 16 + tig * 2, c1 = c0 + 8;
            aqh[kk][0] = *reinterpret_cast<const uint32_t*>(&sKh[r0][c0]);
            aqh[kk][1] = *reinterpret_cast<const uint32_t*>(&sKh[r1][c0]);
            aqh[kk][2] = *reinterpret_cast<const uint32_t*>(&sKh[r0][c1]);
            aqh[kk][3] = *reinterpret_cast<const uint32_t*>(&sKh[r1][c1]);
            aql[kk][0] = *reinterpret_cast<const uint32_t*>(&sKl[r0][c0]);
            aql[kk][1] = *reinterpret_cast<const uint32_t*>(&sKl[r1][c0]);
            aql[kk][2] = *reinterpret_cast<const uint32_t*>(&sKl[r0][c1]);
            aql[kk][3] = *reinterpret_cast<const uint32_t*>(&sKl[r1][c1]);
        }
    }

    float m0 = -1e30f, m1 = -1e30f, l0 = 0.0f, l1 = 0.0f;
    float O[8][4];
#pragma unroll
    for (int dt = 0; dt < 8; dt++)
#pragma unroll
        for (int v = 0; v < 4; v++) O[dt][v] = 0.0f;

    for (int jb = 0; jb <= qt; jb++) {
        __syncthreads();
        // Load K hi/lo
        {
            int row = tid >> 1, half = tid & 1;
            size_t go = ((size_t)(b * Tdim + jb * 64 + row)) * C3 + Cdim + h * Ddim + half * 32;
            const uint4* gh = reinterpret_cast<const uint4*>(qvh + go);
            const uint4* gl = reinterpret_cast<const uint4*>(qvl + go);
            uint4* dh = reinterpret_cast<uint4*>(&sKh[row][half * 32]);
            uint4* dl = reinterpret_cast<uint4*>(&sKl[row][half * 32]);
#pragma unroll
            for (int i = 0; i < 4; i++) { dh[i] = gh[i]; dl[i] = gl[i]; }
        }
        // Load V transposed: sV[d][k]
        {
            int k = tid >> 1, dbase = (tid & 1) * 32;
            size_t go = ((size_t)(b * Tdim + jb * 64 + k)) * C3 + 2 * Cdim + h * Ddim + dbase;
            uint4 hv[4], lv[4];
#pragma unroll
            for (int i = 0; i < 4; i++) {
                hv[i] = reinterpret_cast<const uint4*>(qvh + go)[i];
                lv[i] = reinterpret_cast<const uint4*>(qvl + go)[i];
            }
#pragma unroll
            for (int i = 0; i < 4; i++) {
                const unsigned short* ph = reinterpret_cast<const unsigned short*>(&hv[i]);
                const unsigned short* pl = reinterpret_cast<const unsigned short*>(&lv[i]);
#pragma unroll
                for (int e = 0; e < 8; e++) {
                    sVh[dbase + i * 8 + e][k] = ph[e];
                    sVl[dbase + i * 8 + e][k] = pl[e];
                }
            }
        }
        __syncthreads();

        // S = Q K^T (3 passes)
        float S[8][4];
#pragma unroll
        for (int nt = 0; nt < 8; nt++)
#pragma unroll
            for (int v = 0; v < 4; v++) S[nt][v] = 0.0f;
#pragma unroll
        for (int kk = 0; kk < 4; kk++) {
            int c0 = kk * 16 + tig * 2, c1 = c0 + 8;
#pragma unroll
            for (int nt = 0; nt < 8; nt++) {
                int n = nt * 8 + g;
                uint32_t kh0 = *reinterpret_cast<const uint32_t*>(&sKh[n][c0]);
                uint32_t kh1 = *reinterpret_cast<const uint32_t*>(&sKh[n][c1]);
                uint32_t kl0 = *reinterpret_cast<const uint32_t*>(&sKl[n][c0]);
                uint32_t kl1 = *reinterpret_cast<const uint32_t*>(&sKl[n][c1]);
                mma_bf16(S[nt], aqh[kk][0], aqh[kk][1], aqh[kk][2], aqh[kk][3], kh0, kh1);
                mma_bf16(S[nt], aqh[kk][0], aqh[kk][1], aqh[kk][2], aqh[kk][3], kl0, kl1);
                mma_bf16(S[nt], aql[kk][0], aql[kk][1], aql[kk][2], aql[kk][3], kh0, kh1);
            }
        }

        // Scale + causal mask
        const int lq0 = w * 16 + g, lq1 = lq0 + 8;
#pragma unroll
        for (int nt = 0; nt < 8; nt++) {
            int lj = nt * 8 + tig * 2;
            S[nt][0] *= 0.125f; S[nt][1] *= 0.125f;
            S[nt][2] *= 0.125f; S[nt][3] *= 0.125f;
            if (jb == qt) {
                if (lj     > lq0) S[nt][0] = -1e30f;
                if (lj + 1 > lq0) S[nt][1] = -1e30f;
                if (lj     > lq1) S[nt][2] = -1e30f;
                if (lj + 1 > lq1) S[nt][3] = -1e30f;
            }
        }

        // Online softmax
        float tm0 = -1e30f, tm1 = -1e30f;
#pragma unroll
        for (int nt = 0; nt < 8; nt++) {
            tm0 = fmaxf(tm0, fmaxf(S[nt][0], S[nt][1]));
            tm1 = fmaxf(tm1, fmaxf(S[nt][2], S[nt][3]));
        }
        tm0 = fmaxf(tm0, __shfl_xor_sync(0xffffffffu, tm0, 1));
        tm0 = fmaxf(tm0, __shfl_xor_sync(0xffffffffu, tm0, 2));
        tm1 = fmaxf(tm1, __shfl_xor_sync(0xffffffffu, tm1, 1));
        tm1 = fmaxf(tm1, __shfl_xor_sync(0xffffffffu, tm1, 2));
        float mn0 = fmaxf(m0, tm0), mn1 = fmaxf(m1, tm1);
        float al0 = __expf(m0 - mn0), al1 = __expf(m1 - mn1);
        m0 = mn0; m1 = mn1;
        l0 *= al0; l1 *= al1;
#pragma unroll
        for (int dt = 0; dt < 8; dt++) {
            O[dt][0] *= al0; O[dt][1] *= al0;
            O[dt][2] *= al1; O[dt][3] *= al1;
        }

        // P hi/lo split; l from (p_hi + p_lo)
        float rs0 = 0.0f, rs1 = 0.0f;
        uint32_t aPh[4][4], aPl[4][4];
#pragma unroll
        for (int nt = 0; nt < 8; nt++) {
            float p0 = __expf(S[nt][0] - m0);
            float p1 = __expf(S[nt][1] - m0);
            float p2 = __expf(S[nt][2] - m1);
            float p3 = __expf(S[nt][3] - m1);
            float p0h = bf16_round(p0), p1h = bf16_round(p1);
            float p2h = bf16_round(p2), p3h = bf16_round(p3);
            float p0l = bf16_round(p0 - p0h), p1l = bf16_round(p1 - p1h);
            float p2l = bf16_round(p2 - p2h), p3l = bf16_round(p3 - p3h);
            rs0 += (p0h + p0l) + (p1h + p1l);
            rs1 += (p2h + p2l) + (p3h + p3l);
            int kk = nt >> 1, hf = (nt & 1) * 2;
            aPh[kk][hf + 0] = bf16x2_pack(p0h, p1h);
            aPh[kk][hf + 1] = bf16x2_pack(p2h, p3h);
            aPl[kk][hf + 0] = bf16x2_pack(p0l, p1l);
            aPl[kk][hf + 1] = bf16x2_pack(p2l, p3l);
        }
        rs0 += __shfl_xor_sync(0xffffffffu, rs0, 1);
        rs0 += __shfl_xor_sync(0xffffffffu, rs0, 2);
        rs1 += __shfl_xor_sync(0xffffffffu, rs1, 1);
        rs1 += __shfl_xor_sync(0xffffffffu, rs1, 2);
        l0 += rs0; l1 += rs1;

        // O += Ph*Vh + Ph*Vl + Pl*Vh
#pragma unroll
        for (int kk = 0; kk < 4; kk++) {
            int c0 = kk * 16 + tig * 2, c1 = c0 + 8;
#pragma unroll
            for (int dt = 0; dt < 8; dt++) {
                int n = dt * 8 + g;
                uint32_t vh0 = *reinterpret_cast<const uint32_t*>(&sVh[n][c0]);
                uint32_t vh1 = *reinterpret_cast<const uint32_t*>(&sVh[n][c1]);
                uint32_t vl0 = *reinterpret_cast<const uint32_t*>(&sVl[n][c0]);
                uint32_t vl1 = *reinterpret_cast<const uint32_t*>(&sVl[n][c1]);
                mma_bf16(O[dt], aPh[kk][0], aPh[kk][1], aPh[kk][2], aPh[kk][3], vh0, vh1);
                mma_bf16(O[dt], aPh[kk][0], aPh[kk][1], aPh[kk][2], aPh[kk][3], vl0, vl1);
                mma_bf16(O[dt], aPl[kk][0], aPl[kk][1], aPl[kk][2], aPl[kk][3], vh0, vh1);
            }
        }
    }

    // Epilogue: write bf16 hi/lo directly (fused split for proj GEMM)
    float inv0 = 1.0f / l0, inv1 = 1.0f / l1;
    int r0 = q0 + w * 16 + g, r1 = r0 + 8;
    size_t o0 = ((size_t)(b * Tdim + r0)) * Cdim + h * Ddim;
    size_t o1 = ((size_t)(b * Tdim + r1)) * Cdim + h * Ddim;
#pragma unroll
    for (int dt = 0; dt < 8; dt++) {
        int d = dt * 8 + tig * 2;
        float v00 = O[dt][0] * inv0, v01 = O[dt][1] * inv0;
        float v10 = O[dt][2] * inv1, v11 = O[dt][3] * inv1;
        float h00 = bf16_round(v00), h01 = bf16_round(v01);
        float h10 = bf16_round(v10), h11 = bf16_round(v11);
        *reinterpret_cast<uint32_t*>(outHi + o0 + d) = bf16x2_pack(h00, h01);
        *reinterpret_cast<uint32_t*>(outHi + o1 + d) = bf16x2_pack(h10, h11);
        *reinterpret_cast<uint32_t*>(outLo + o0 + d) = bf16x2_pack(v00 - h00, v01 - h01);
        *reinterpret_cast<uint32_t*>(outLo + o1 + d) = bf16x2_pack(v10 - h10, v11 - h11);
    }
}

// ---------------------------------------------------------------------------
extern "C" void kernel_launch(void* const* d_in, const int* in_sizes, int n_in,
                              void* d_out, int out_size)
{
    (void)in_sizes; (void)n_in; (void)out_size;
    const float* x      = (const float*)d_in[0];
    const float* W_attn = (const float*)d_in[1];
    const float* b_attn = (const float*)d_in[2];
    const float* W_proj = (const float*)d_in[3];
    const float* b_proj = (const float*)d_in[4];
    float* out = (float*)d_out;

    unsigned short *x_hi, *x_lo, *Wa_hi, *Wa_lo, *Wp_hi, *Wp_lo, *ah_hi, *ah_lo, *qkv_hi, *qkv_lo;
    cudaGetSymbolAddress((void**)&x_hi, g_x_hi);
    cudaGetSymbolAddress((void**)&x_lo, g_x_lo);
    cudaGetSymbolAddress((void**)&Wa_hi, g_Wa_hi);
    cudaGetSymbolAddress((void**)&Wa_lo, g_Wa_lo);
    cudaGetSymbolAddress((void**)&Wp_hi, g_Wp_hi);
    cudaGetSymbolAddress((void**)&Wp_lo, g_Wp_lo);
    cudaGetSymbolAddress((void**)&ah_hi, g_ah_hi);
    cudaGetSymbolAddress((void**)&ah_lo, g_ah_lo);
    cudaGetSymbolAddress((void**)&qkv_hi, g_qkv_hi);
    cudaGetSymbolAddress((void**)&qkv_lo, g_qkv_lo);

    cudaFuncSetAttribute(gemm_mma_kernel,
                         cudaFuncAttributeMaxDynamicSharedMemorySize, GEMM_SMEM_BYTES);

    // Split inputs to bf16 hi/lo (weights transposed to [N,K])
    {
        int n = Mrows * Cdim;
        split_kernel<<<(n + 255) / 256, 256>>>(x, x_hi, x_lo, n);
        splitT_kernel<<<dim3(C3 / 32, Cdim / 32), 256>>>(W_attn, Wa_hi, Wa_lo, Cdim, C3);
        splitT_kernel<<<dim3(Cdim / 32, Cdim / 32), 256>>>(W_proj, Wp_hi, Wp_lo, Cdim, Cdim);
    }
    // 1) QKV = x @ W_attn + b_attn  -> bf16 hi/lo directly (fused split)
    gemm_mma_kernel<<<dim3(C3 / BN, Mrows / BM), 256, GEMM_SMEM_BYTES>>>(
        x_hi, x_lo, Wa_hi, Wa_lo, b_attn, nullptr, qkv_hi, qkv_lo, Mrows, C3, Cdim);
    // 2) Tensor-core flash attention -> bf16 hi/lo directly (fused split)
    attn_mma_kernel<<<dim3(Tdim / 64, Bdim * Hdim), 128>>>(qkv_hi, qkv_lo, ah_hi, ah_lo);
    // 3) out = att @ W_proj + b_proj  (fp32 epilogue)
    gemm_mma_kernel<<<dim3(Cdim / BN, Mrows / BM), 256, GEMM_SMEM_BYTES>>>(
        ah_hi, ah_lo, Wp_hi, Wp_lo, b_proj, out, nullptr, nullptr, Mrows, Cdim, Cdim);
}

// round 10
// speedup vs baseline: 3.2833x; 1.0969x over previous
#include <cuda_runtime.h>
#include <cuda_bf16.h>
#include <cstdint>
#include <cstddef>

#define Bdim 4
#define Tdim 2048
#define Cdim 1024
#define Hdim 16
#define Ddim 64
#define C3   3072
#define Mrows 8192

// bf16 hi/lo scratch
__device__ unsigned short g_x_hi[(size_t)Mrows * Cdim];
__device__ unsigned short g_x_lo[(size_t)Mrows * Cdim];
__device__ unsigned short g_Wa_hi[(size_t)C3 * Cdim];   // transposed [N=3072][K=1024]
__device__ unsigned short g_Wa_lo[(size_t)C3 * Cdim];
__device__ unsigned short g_Wp_hi[(size_t)Cdim * Cdim]; // transposed [N=1024][K=1024]
__device__ unsigned short g_Wp_lo[(size_t)Cdim * Cdim];
__device__ unsigned short g_ah_hi[(size_t)Mrows * Cdim];
__device__ unsigned short g_ah_lo[(size_t)Mrows * Cdim];
__device__ unsigned short g_qkv_hi[(size_t)Mrows * C3];
__device__ unsigned short g_qkv_lo[(size_t)Mrows * C3];

// ---------------------------------------------------------------------------
// PTX helpers (compute_103-safe)
// ---------------------------------------------------------------------------
__device__ __forceinline__ void mma_bf16(float* d,
    uint32_t a0, uint32_t a1, uint32_t a2, uint32_t a3,
    uint32_t b0, uint32_t b1)
{
    asm volatile(
        "mma.sync.aligned.m16n8k16.row.col.f32.bf16.bf16.f32 "
        "{%0,%1,%2,%3}, {%4,%5,%6,%7}, {%8,%9}, {%0,%1,%2,%3};"
        : "+f"(d[0]), "+f"(d[1]), "+f"(d[2]), "+f"(d[3])
        : "r"(a0), "r"(a1), "r"(a2), "r"(a3), "r"(b0), "r"(b1));
}
__device__ __forceinline__ void ldmatrix_x4(uint32_t* r, uint32_t addr) {
    asm volatile("ldmatrix.sync.aligned.m8n8.x4.shared.b16 {%0,%1,%2,%3}, [%4];"
        : "=r"(r[0]), "=r"(r[1]), "=r"(r[2]), "=r"(r[3]) : "r"(addr));
}
__device__ __forceinline__ void ldmatrix_x4_trans(uint32_t* r, uint32_t addr) {
    asm volatile("ldmatrix.sync.aligned.m8n8.x4.trans.shared.b16 {%0,%1,%2,%3}, [%4];"
        : "=r"(r[0]), "=r"(r[1]), "=r"(r[2]), "=r"(r[3]) : "r"(addr));
}
__device__ __forceinline__ uint32_t smem_u32(const void* p) {
    return (uint32_t)__cvta_generic_to_shared(p);
}
__device__ __forceinline__ uint32_t bf16x2_pack(float lo, float hi) {
    uint32_t r;
    asm("cvt.rn.bf16x2.f32 %0, %1, %2;" : "=r"(r) : "f"(hi), "f"(lo));
    return r;
}
__device__ __forceinline__ float bf16_round(float x) {
    __nv_bfloat16 h = __float2bfloat16(x);
    return __bfloat162float(h);
}
__device__ __forceinline__ void cp_async16(void* smem_dst, const void* gsrc) {
    uint32_t sa = smem_u32(smem_dst);
    asm volatile("cp.async.cg.shared.global [%0], [%1], 16;" :: "r"(sa), "l"(gsrc) : "memory");
}
__device__ __forceinline__ void cp_async_commit() {
    asm volatile("cp.async.commit_group;" ::: "memory");
}
template<int N> __device__ __forceinline__ void cp_async_wait() {
    asm volatile("cp.async.wait_group %0;" :: "n"(N) : "memory");
}

// ---------------------------------------------------------------------------
// hi/lo split kernels (inputs only)
// ---------------------------------------------------------------------------
__global__ __launch_bounds__(256) void split_kernel(
    const float* __restrict__ in, unsigned short* __restrict__ hi,
    unsigned short* __restrict__ lo, int n)
{
    int i = blockIdx.x * 256 + threadIdx.x;
    if (i >= n) return;
    float x = in[i];
    __nv_bfloat16 h = __float2bfloat16(x);
    float r = x - __bfloat162float(h);
    __nv_bfloat16 l = __float2bfloat16(r);
    hi[i] = *reinterpret_cast<unsigned short*>(&h);
    lo[i] = *reinterpret_cast<unsigned short*>(&l);
}

__global__ __launch_bounds__(256) void splitT_kernel(
    const float* __restrict__ W, unsigned short* __restrict__ hiT,
    unsigned short* __restrict__ loT, int K, int N)
{
    __shared__ float t[32][33];
    int bn = blockIdx.x * 32;
    int bk = blockIdx.y * 32;
    int tx = threadIdx.x & 31;
    int ty = threadIdx.x >> 5;
#pragma unroll
    for (int i = ty; i < 32; i += 8)
        t[i][tx] = W[(size_t)(bk + i) * N + bn + tx];
    __syncthreads();
#pragma unroll
    for (int i = ty; i < 32; i += 8) {
        float x = t[tx][i];
        __nv_bfloat16 h = __float2bfloat16(x);
        float r = x - __bfloat162float(h);
        __nv_bfloat16 l = __float2bfloat16(r);
        size_t o = (size_t)(bn + i) * K + bk + tx;
        hiT[o] = *reinterpret_cast<unsigned short*>(&h);
        loT[o] = *reinterpret_cast<unsigned short*>(&l);
    }
}

// ---------------------------------------------------------------------------
// GEMM: cp.async double-buffered + ldmatrix fragment loads.
// ---------------------------------------------------------------------------
#define BM 128
#define BN 128
#define BK 32
#define PAD 40
#define GTILE (128 * PAD)
#define GBUF  (4 * GTILE)
#define GEMM_SMEM_BYTES (2 * GBUF * 2)

__global__ __launch_bounds__(256, 2) void gemm_mma_kernel(
    const unsigned short* __restrict__ Ah, const unsigned short* __restrict__ Al,
    const unsigned short* __restrict__ Bh, const unsigned short* __restrict__ Bl,
    const float* __restrict__ bias, float* __restrict__ C,
    unsigned short* __restrict__ OHi, unsigned short* __restrict__ OLo,
    int M, int N, int K)
{
    extern __shared__ unsigned short sm[];

    const int tid = threadIdx.x;
    const int wid = tid >> 5;
    const int lane = tid & 31;
    const int g   = lane >> 2;
    const int tig = lane & 3;
    const int lgrp = lane >> 3;     // 0..3 (ldmatrix quadrant)
    const int lrow = lane & 7;      // row within quadrant
    const int wm  = wid & 3;
    const int wn  = wid >> 2;
    const int bm  = blockIdx.y * BM;
    const int bn  = blockIdx.x * BN;

    float acc[2][8][4];
#pragma unroll
    for (int i = 0; i < 2; i++)
#pragma unroll
        for (int j = 0; j < 8; j++)
#pragma unroll
            for (int v = 0; v < 4; v++) acc[i][j][v] = 0.0f;

    const int lr = tid >> 1;
    const int lh = tid & 1;
    const int nk = K / BK;

    auto load_tile = [&](int s, int buf) {
        const int k0 = s * BK;
        unsigned short* base = sm + buf * GBUF + lr * PAD + lh * 16;
        const size_t aoff = (size_t)(bm + lr) * K + k0 + lh * 16;
        const size_t boff = (size_t)(bn + lr) * K + k0 + lh * 16;
        cp_async16(base + 0 * GTILE,     Ah + aoff);
        cp_async16(base + 0 * GTILE + 8, Ah + aoff + 8);
        cp_async16(base + 1 * GTILE,     Al + aoff);
        cp_async16(base + 1 * GTILE + 8, Al + aoff + 8);
        cp_async16(base + 2 * GTILE,     Bh + boff);
        cp_async16(base + 2 * GTILE + 8, Bh + boff + 8);
        cp_async16(base + 3 * GTILE,     Bl + boff);
        cp_async16(base + 3 * GTILE + 8, Bl + boff + 8);
    };

    load_tile(0, 0);
    cp_async_commit();

    // ldmatrix row/col offsets within a fragment load
    const int a_ro = (lgrp & 1) * 8 + lrow;   // A/B-quadrant row
    const int a_co = (lgrp >> 1) * 8;         // A column half
    const int b_ro = (lgrp >> 1) * 8 + lrow;  // B row (n) offset
    const int b_co = (lgrp & 1) * 8;          // B column half

    for (int s = 0; s < nk; s++) {
        if (s + 1 < nk) {
            load_tile(s + 1, (s + 1) & 1);
            cp_async_commit();
            cp_async_wait<1>();
        } else {
            cp_async_wait<0>();
        }
        __syncthreads();

        const unsigned short* pAh = sm + (s & 1) * GBUF;
        const unsigned short* pAl = pAh + GTILE;
        const unsigned short* pBh = pAl + GTILE;
        const unsigned short* pBl = pBh + GTILE;

#pragma unroll
        for (int ks = 0; ks < 2; ks++) {
            const int kb = ks * 16;
            uint32_t ah[2][4], al[2][4];
#pragma unroll
            for (int mt = 0; mt < 2; mt++) {
                int off = (wm * 32 + mt * 16 + a_ro) * PAD + kb + a_co;
                ldmatrix_x4(ah[mt], smem_u32(pAh + off));
                ldmatrix_x4(al[mt], smem_u32(pAl + off));
            }
#pragma unroll
            for (int p = 0; p < 4; p++) {
                int off = (wn * 64 + p * 16 + b_ro) * PAD + kb + b_co;
                uint32_t bh[4], bl[4];
                ldmatrix_x4(bh, smem_u32(pBh + off));
                ldmatrix_x4(bl, smem_u32(pBl + off));
#pragma unroll
                for (int mt = 0; mt < 2; mt++) {
                    mma_bf16(acc[mt][2*p],   ah[mt][0], ah[mt][1], ah[mt][2], ah[mt][3], bh[0], bh[1]);
                    mma_bf16(acc[mt][2*p],   ah[mt][0], ah[mt][1], ah[mt][2], ah[mt][3], bl[0], bl[1]);
                    mma_bf16(acc[mt][2*p],   al[mt][0], al[mt][1], al[mt][2], al[mt][3], bh[0], bh[1]);
                    mma_bf16(acc[mt][2*p+1], ah[mt][0], ah[mt][1], ah[mt][2], ah[mt][3], bh[2], bh[3]);
                    mma_bf16(acc[mt][2*p+1], ah[mt][0], ah[mt][1], ah[mt][2], ah[mt][3], bl[2], bl[3]);
                    mma_bf16(acc[mt][2*p+1], al[mt][0], al[mt][1], al[mt][2], al[mt][3], bh[2], bh[3]);
                }
            }
        }
        __syncthreads();
    }

    // Epilogue
#pragma unroll
    for (int mt = 0; mt < 2; mt++) {
        int r0 = bm + wm * 32 + mt * 16 + g;
        int r1 = r0 + 8;
#pragma unroll
        for (int nt = 0; nt < 8; nt++) {
            int col = bn + wn * 64 + nt * 8 + tig * 2;
            float b0 = bias[col], b1 = bias[col + 1];
            float v00 = acc[mt][nt][0] + b0, v01 = acc[mt][nt][1] + b1;
            float v10 = acc[mt][nt][2] + b0, v11 = acc[mt][nt][3] + b1;
            if (C) {
                *reinterpret_cast<float2*>(C + (size_t)r0 * N + col) = make_float2(v00, v01);
                *reinterpret_cast<float2*>(C + (size_t)r1 * N + col) = make_float2(v10, v11);
            } else {
                float h00 = bf16_round(v00), h01 = bf16_round(v01);
                float h10 = bf16_round(v10), h11 = bf16_round(v11);
                *reinterpret_cast<uint32_t*>(OHi + (size_t)r0 * N + col) = bf16x2_pack(h00, h01);
                *reinterpret_cast<uint32_t*>(OHi + (size_t)r1 * N + col) = bf16x2_pack(h10, h11);
                *reinterpret_cast<uint32_t*>(OLo + (size_t)r0 * N + col) = bf16x2_pack(v00 - h00, v01 - h01);
                *reinterpret_cast<uint32_t*>(OLo + (size_t)r1 * N + col) = bf16x2_pack(v10 - h10, v11 - h11);
            }
        }
    }
}

// ---------------------------------------------------------------------------
// Tensor-core causal flash attention with ldmatrix.
// V stored naturally [k][d]; PV B-fragments via ldmatrix.x4.trans.
// ---------------------------------------------------------------------------
#define APAD 72

__global__ __launch_bounds__(128) void attn_mma_kernel(
    const unsigned short* __restrict__ qvh, const unsigned short* __restrict__ qvl,
    unsigned short* __restrict__ outHi, unsigned short* __restrict__ outLo)
{
    __shared__ __align__(16) unsigned short sKh[64][APAD], sKl[64][APAD];  // Q first, then K
    __shared__ __align__(16) unsigned short sVh[64][APAD], sVl[64][APAD];  // [k][d]

    const int tid = threadIdx.x;
    const int w = tid >> 5, lane = tid & 31;
    const int g = lane >> 2, tig = lane & 3;
    const int lgrp = lane >> 3, lrow = lane & 7;
    const int bh = blockIdx.y, b = bh >> 4, h = bh & 15;
    const int qt = blockIdx.x, q0 = qt * 64;

    // Load Q hi/lo tile into the K buffers
    {
        int row = tid >> 1, half = tid & 1;
        size_t go = ((size_t)(b * Tdim + q0 + row)) * C3 + h * Ddim + half * 32;
        const uint4* gh = reinterpret_cast<const uint4*>(qvh + go);
        const uint4* gl = reinterpret_cast<const uint4*>(qvl + go);
        uint4* dh = reinterpret_cast<uint4*>(&sKh[row][half * 32]);
        uint4* dl = reinterpret_cast<uint4*>(&sKl[row][half * 32]);
#pragma unroll
        for (int i = 0; i < 4; i++) { dh[i] = gh[i]; dl[i] = gl[i]; }
    }
    __syncthreads();

    // Hoist Q fragments via ldmatrix; Q smem dead afterwards
    uint32_t aqh[4][4], aql[4][4];
    {
        const int ro = w * 16 + (lgrp & 1) * 8 + lrow;
#pragma unroll
        for (int kk = 0; kk < 4; kk++) {
            int co = kk * 16 + (lgrp >> 1) * 8;
            ldmatrix_x4(aqh[kk], smem_u32(&sKh[ro][co]));
            ldmatrix_x4(aql[kk], smem_u32(&sKl[ro][co]));
        }
    }

    float m0 = -1e30f, m1 = -1e30f, l0 = 0.0f, l1 = 0.0f;
    float O[8][4];
#pragma unroll
    for (int dt = 0; dt < 8; dt++)
#pragma unroll
        for (int v = 0; v < 4; v++) O[dt][v] = 0.0f;

    // ldmatrix offsets
    const int kb_ro = (lgrp >> 1) * 8 + lrow;   // K: row (n) offset
    const int kb_co = (lgrp & 1) * 8;           // K: col half
    const int vt_ro = (lgrp & 1) * 8 + lrow;    // V-trans: stored row (k) offset
    const int vt_co = (lgrp >> 1) * 8;          // V-trans: stored col (d) half

    for (int jb = 0; jb <= qt; jb++) {
        __syncthreads();
        // Load K hi/lo [n][k] and V hi/lo [k][d] — identical coalesced pattern
        {
            int row = tid >> 1, half = tid & 1;
            size_t gk = ((size_t)(b * Tdim + jb * 64 + row)) * C3 + Cdim + h * Ddim + half * 32;
            size_t gv = gk + Cdim;
            const uint4* kh = reinterpret_cast<const uint4*>(qvh + gk);
            const uint4* kl = reinterpret_cast<const uint4*>(qvl + gk);
            const uint4* vh = reinterpret_cast<const uint4*>(qvh + gv);
            const uint4* vl = reinterpret_cast<const uint4*>(qvl + gv);
            uint4* dkh = reinterpret_cast<uint4*>(&sKh[row][half * 32]);
            uint4* dkl = reinterpret_cast<uint4*>(&sKl[row][half * 32]);
            uint4* dvh = reinterpret_cast<uint4*>(&sVh[row][half * 32]);
            uint4* dvl = reinterpret_cast<uint4*>(&sVl[row][half * 32]);
#pragma unroll
            for (int i = 0; i < 4; i++) {
                dkh[i] = kh[i]; dkl[i] = kl[i];
                dvh[i] = vh[i]; dvl[i] = vl[i];
            }
        }
        __syncthreads();

        // S = Q K^T (3 passes), fragments via ldmatrix
        float S[8][4];
#pragma unroll
        for (int nt = 0; nt < 8; nt++)
#pragma unroll
            for (int v = 0; v < 4; v++) S[nt][v] = 0.0f;
#pragma unroll
        for (int kk = 0; kk < 4; kk++) {
            const int kb = kk * 16;
#pragma unroll
            for (int p = 0; p < 4; p++) {
                uint32_t kh[4], kl[4];
                int off_r = p * 16 + kb_ro;
                ldmatrix_x4(kh, smem_u32(&sKh[off_r][kb + kb_co]));
                ldmatrix_x4(kl, smem_u32(&sKl[off_r][kb + kb_co]));
                mma_bf16(S[2*p],   aqh[kk][0], aqh[kk][1], aqh[kk][2], aqh[kk][3], kh[0], kh[1]);
                mma_bf16(S[2*p],   aqh[kk][0], aqh[kk][1], aqh[kk][2], aqh[kk][3], kl[0], kl[1]);
                mma_bf16(S[2*p],   aql[kk][0], aql[kk][1], aql[kk][2], aql[kk][3], kh[0], kh[1]);
                mma_bf16(S[2*p+1], aqh[kk][0], aqh[kk][1], aqh[kk][2], aqh[kk][3], kh[2], kh[3]);
                mma_bf16(S[2*p+1], aqh[kk][0], aqh[kk][1], aqh[kk][2], aqh[kk][3], kl[2], kl[3]);
                mma_bf16(S[2*p+1], aql[kk][0], aql[kk][1], aql[kk][2], aql[kk][3], kh[2], kh[3]);
            }
        }

        // Scale + causal mask
        const int lq0 = w * 16 + g, lq1 = lq0 + 8;
#pragma unroll
        for (int nt = 0; nt < 8; nt++) {
            int lj = nt * 8 + tig * 2;
            S[nt][0] *= 0.125f; S[nt][1] *= 0.125f;
            S[nt][2] *= 0.125f; S[nt][3] *= 0.125f;
            if (jb == qt) {
                if (lj     > lq0) S[nt][0] = -1e30f;
                if (lj + 1 > lq0) S[nt][1] = -1e30f;
                if (lj     > lq1) S[nt][2] = -1e30f;
                if (lj + 1 > lq1) S[nt][3] = -1e30f;
            }
        }

        // Online softmax
        float tm0 = -1e30f, tm1 = -1e30f;
#pragma unroll
        for (int nt = 0; nt < 8; nt++) {
            tm0 = fmaxf(tm0, fmaxf(S[nt][0], S[nt][1]));
            tm1 = fmaxf(tm1, fmaxf(S[nt][2], S[nt][3]));
        }
        tm0 = fmaxf(tm0, __shfl_xor_sync(0xffffffffu, tm0, 1));
        tm0 = fmaxf(tm0, __shfl_xor_sync(0xffffffffu, tm0, 2));
        tm1 = fmaxf(tm1, __shfl_xor_sync(0xffffffffu, tm1, 1));
        tm1 = fmaxf(tm1, __shfl_xor_sync(0xffffffffu, tm1, 2));
        float mn0 = fmaxf(m0, tm0), mn1 = fmaxf(m1, tm1);
        float al0 = __expf(m0 - mn0), al1 = __expf(m1 - mn1);
        m0 = mn0; m1 = mn1;
        l0 *= al0; l1 *= al1;
#pragma unroll
        for (int dt = 0; dt < 8; dt++) {
            O[dt][0] *= al0; O[dt][1] *= al0;
            O[dt][2] *= al1; O[dt][3] *= al1;
        }

        // P hi/lo split; l from (p_hi + p_lo)
        float rs0 = 0.0f, rs1 = 0.0f;
        uint32_t aPh[4][4], aPl[4][4];
#pragma unroll
        for (int nt = 0; nt < 8; nt++) {
            float p0 = __expf(S[nt][0] - m0);
            float p1 = __expf(S[nt][1] - m0);
            float p2 = __expf(S[nt][2] - m1);
            float p3 = __expf(S[nt][3] - m1);
            float p0h = bf16_round(p0), p1h = bf16_round(p1);
            float p2h = bf16_round(p2), p3h = bf16_round(p3);
            float p0l = bf16_round(p0 - p0h), p1l = bf16_round(p1 - p1h);
            float p2l = bf16_round(p2 - p2h), p3l = bf16_round(p3 - p3h);
            rs0 += (p0h + p0l) + (p1h + p1l);
            rs1 += (p2h + p2l) + (p3h + p3l);
            int kk = nt >> 1, hf = (nt & 1) * 2;
            aPh[kk][hf + 0] = bf16x2_pack(p0h, p1h);
            aPh[kk][hf + 1] = bf16x2_pack(p2h, p3h);
            aPl[kk][hf + 0] = bf16x2_pack(p0l, p1l);
            aPl[kk][hf + 1] = bf16x2_pack(p2l, p3l);
        }
        rs0 += __shfl_xor_sync(0xffffffffu, rs0, 1);
        rs0 += __shfl_xor_sync(0xffffffffu, rs0, 2);
        rs1 += __shfl_xor_sync(0xffffffffu, rs1, 1);
        rs1 += __shfl_xor_sync(0xffffffffu, rs1, 2);
        l0 += rs0; l1 += rs1;

        // O += Ph*Vh + Ph*Vl + Pl*Vh; V^T fragments via ldmatrix.trans
#pragma unroll
        for (int kk = 0; kk < 4; kk++) {
            const int kb = kk * 16;
#pragma unroll
            for (int p = 0; p < 4; p++) {
                uint32_t vh[4], vl[4];
                int off_r = kb + vt_ro;
                int off_c = p * 16 + vt_co;
                ldmatrix_x4_trans(vh, smem_u32(&sVh[off_r][off_c]));
                ldmatrix_x4_trans(vl, smem_u32(&sVl[off_r][off_c]));
                mma_bf16(O[2*p],   aPh[kk][0], aPh[kk][1], aPh[kk][2], aPh[kk][3], vh[0], vh[1]);
                mma_bf16(O[2*p],   aPh[kk][0], aPh[kk][1], aPh[kk][2], aPh[kk][3], vl[0], vl[1]);
                mma_bf16(O[2*p],   aPl[kk][0], aPl[kk][1], aPl[kk][2], aPl[kk][3], vh[0], vh[1]);
                mma_bf16(O[2*p+1], aPh[kk][0], aPh[kk][1], aPh[kk][2], aPh[kk][3], vh[2], vh[3]);
                mma_bf16(O[2*p+1], aPh[kk][0], aPh[kk][1], aPh[kk][2], aPh[kk][3], vl[2], vl[3]);
                mma_bf16(O[2*p+1], aPl[kk][0], aPl[kk][1], aPl[kk][2], aPl[kk][3], vh[2], vh[3]);
            }
        }
    }

    // Epilogue: write bf16 hi/lo directly (fused split for proj GEMM)
    float inv0 = 1.0f / l0, inv1 = 1.0f / l1;
    int r0 = q0 + w * 16 + g, r1 = r0 + 8;
    size_t o0 = ((size_t)(b * Tdim + r0)) * Cdim + h * Ddim;
    size_t o1 = ((size_t)(b * Tdim + r1)) * Cdim + h * Ddim;
#pragma unroll
    for (int dt = 0; dt < 8; dt++) {
        int d = dt * 8 + tig * 2;
        float v00 = O[dt][0] * inv0, v01 = O[dt][1] * inv0;
        float v10 = O[dt][2] * inv1, v11 = O[dt][3] * inv1;
        float h00 = bf16_round(v00), h01 = bf16_round(v01);
        float h10 = bf16_round(v10), h11 = bf16_round(v11);
        *reinterpret_cast<uint32_t*>(outHi + o0 + d) = bf16x2_pack(h00, h01);
        *reinterpret_cast<uint32_t*>(outHi + o1 + d) = bf16x2_pack(h10, h11);
        *reinterpret_cast<uint32_t*>(outLo + o0 + d) = bf16x2_pack(v00 - h00, v01 - h01);
        *reinterpret_cast<uint32_t*>(outLo + o1 + d) = bf16x2_pack(v10 - h10, v11 - h11);
    }
}

// ---------------------------------------------------------------------------
extern "C" void kernel_launch(void* const* d_in, const int* in_sizes, int n_in,
                              void* d_out, int out_size)
{
    (void)in_sizes; (void)n_in; (void)out_size;
    const float* x      = (const float*)d_in[0];
    const float* W_attn = (const float*)d_in[1];
    const float* b_attn = (const float*)d_in[2];
    const float* W_proj = (const float*)d_in[3];
    const float* b_proj = (const float*)d_in[4];
    float* out = (float*)d_out;

    unsigned short *x_hi, *x_lo, *Wa_hi, *Wa_lo, *Wp_hi, *Wp_lo, *ah_hi, *ah_lo, *qkv_hi, *qkv_lo;
    cudaGetSymbolAddress((void**)&x_hi, g_x_hi);
    cudaGetSymbolAddress((void**)&x_lo, g_x_lo);
    cudaGetSymbolAddress((void**)&Wa_hi, g_Wa_hi);
    cudaGetSymbolAddress((void**)&Wa_lo, g_Wa_lo);
    cudaGetSymbolAddress((void**)&Wp_hi, g_Wp_hi);
    cudaGetSymbolAddress((void**)&Wp_lo, g_Wp_lo);
    cudaGetSymbolAddress((void**)&ah_hi, g_ah_hi);
    cudaGetSymbolAddress((void**)&ah_lo, g_ah_lo);
    cudaGetSymbolAddress((void**)&qkv_hi, g_qkv_hi);
    cudaGetSymbolAddress((void**)&qkv_lo, g_qkv_lo);

    cudaFuncSetAttribute(gemm_mma_kernel,
                         cudaFuncAttributeMaxDynamicSharedMemorySize, GEMM_SMEM_BYTES);

    // Split inputs to bf16 hi/lo (weights transposed to [N,K])
    {
        int n = Mrows * Cdim;
        split_kernel<<<(n + 255) / 256, 256>>>(x, x_hi, x_lo, n);
        splitT_kernel<<<dim3(C3 / 32, Cdim / 32), 256>>>(W_attn, Wa_hi, Wa_lo, Cdim, C3);
        splitT_kernel<<<dim3(Cdim / 32, Cdim / 32), 256>>>(W_proj, Wp_hi, Wp_lo, Cdim, Cdim);
    }
    // 1) QKV = x @ W_attn + b_attn  -> bf16 hi/lo (fused split)
    gemm_mma_kernel<<<dim3(C3 / BN, Mrows / BM), 256, GEMM_SMEM_BYTES>>>(
        x_hi, x_lo, Wa_hi, Wa_lo, b_attn, nullptr, qkv_hi, qkv_lo, Mrows, C3, Cdim);
    // 2) Tensor-core flash attention -> bf16 hi/lo (fused split)
    attn_mma_kernel<<<dim3(Tdim / 64, Bdim * Hdim), 128>>>(qkv_hi, qkv_lo, ah_hi, ah_lo);
    // 3) out = att @ W_proj + b_proj  (fp32 epilogue)
    gemm_mma_kernel<<<dim3(Cdim / BN, Mrows / BM), 256, GEMM_SMEM_BYTES>>>(
        ah_hi, ah_lo, Wp_hi, Wp_lo, b_proj, out, nullptr, nullptr, Mrows, Cdim, Cdim);
}